// round 5
// baseline (speedup 1.0000x reference)
#include <cuda_runtime.h>
#include <cuda_bf16.h>

// Problem constants
#define BB   4
#define SS   1024
#define EE   1024
#define HH   16
#define DD   64
#define PP   1024
#define NSS  2048          // P + S
#define E3   3072          // 3*E

// ---------------------------------------------------------------------------
// Scratch
// ---------------------------------------------------------------------------
__device__ float g_qkv[(size_t)BB * SS * E3];            // [B*S, 3E]
__device__ float g_scores[(size_t)BB * HH * SS * NSS];   // [B*H, S, NS]
__device__ float g_attn[(size_t)BB * SS * EE];           // [B*S, E]

// ---------------------------------------------------------------------------
// Packed fp32x2 helpers (exact fp32, 2 FMAs per instruction on sm_103a)
// ---------------------------------------------------------------------------
__device__ __forceinline__ unsigned long long dup2(float x) {
    unsigned long long r;
    asm("mov.b64 %0, {%1, %1};" : "=l"(r) : "f"(x));
    return r;
}
__device__ __forceinline__ void ffma2(unsigned long long& d,
                                      unsigned long long a, unsigned long long b) {
    asm("fma.rn.f32x2 %0, %1, %2, %0;" : "+l"(d) : "l"(a), "l"(b));
}
__device__ __forceinline__ float2 unpk(unsigned long long v) {
    float lo, hi;
    asm("mov.b64 {%0, %1}, %2;" : "=f"(lo), "=f"(hi) : "l"(v));
    return make_float2(lo, hi);
}
union F4U { float4 f; unsigned long long u[2]; };

// ---------------------------------------------------------------------------
// Tiled GEMM + bias: C[M,N] = A[M,K] @ B[K,N] + bias[N]
// BM=128, BN=128, BK=32, 256 threads, 8x8 microtile, f32x2 inner product.
// ---------------------------------------------------------------------------
template<int N, int K>
__device__ __forceinline__ void gemm_bias_body(
    const float* __restrict__ A, const float* __restrict__ B,
    const float* __restrict__ bias, float* __restrict__ C)
{
    __shared__ float As[32][132];   // transposed A tile [k][m]
    __shared__ float Bs[32][128];   // B tile [k][n]

    const int tid = threadIdx.x;
    const int tr  = tid >> 4;       // 0..15
    const int tc  = tid & 15;       // 0..15
    const int m0  = blockIdx.y * 128;
    const int n0  = blockIdx.x * 128;

    unsigned long long acc[8][4];
#pragma unroll
    for (int i = 0; i < 8; i++)
#pragma unroll
        for (int j = 0; j < 4; j++) acc[i][j] = 0ull;

    for (int k0 = 0; k0 < K; k0 += 32) {
#pragma unroll
        for (int it = 0; it < 4; it++) {
            int f   = tid + it * 256;        // 1024 float4 = 128 rows x 8
            int row = f >> 3;
            int kq  = (f & 7) * 4;
            float4 v = *reinterpret_cast<const float4*>(&A[(size_t)(m0 + row) * K + k0 + kq]);
            As[kq + 0][row] = v.x; As[kq + 1][row] = v.y;
            As[kq + 2][row] = v.z; As[kq + 3][row] = v.w;
        }
#pragma unroll
        for (int it = 0; it < 4; it++) {
            int f    = tid + it * 256;
            int krow = f >> 5;
            int nc   = (f & 31) * 4;
            *reinterpret_cast<float4*>(&Bs[krow][nc]) =
                *reinterpret_cast<const float4*>(&B[(size_t)(k0 + krow) * N + n0 + nc]);
        }
        __syncthreads();

#pragma unroll
        for (int k = 0; k < 32; k++) {
            F4U a0, a1, b0, b1;
            a0.f = *reinterpret_cast<const float4*>(&As[k][tr * 8]);
            a1.f = *reinterpret_cast<const float4*>(&As[k][tr * 8 + 4]);
            b0.f = *reinterpret_cast<const float4*>(&Bs[k][tc * 8]);
            b1.f = *reinterpret_cast<const float4*>(&Bs[k][tc * 8 + 4]);
            float av[8] = {a0.f.x, a0.f.y, a0.f.z, a0.f.w,
                           a1.f.x, a1.f.y, a1.f.z, a1.f.w};
#pragma unroll
            for (int i = 0; i < 8; i++) {
                unsigned long long ai = dup2(av[i]);
                ffma2(acc[i][0], ai, b0.u[0]);
                ffma2(acc[i][1], ai, b0.u[1]);
                ffma2(acc[i][2], ai, b1.u[0]);
                ffma2(acc[i][3], ai, b1.u[1]);
            }
        }
        __syncthreads();
    }

#pragma unroll
    for (int i = 0; i < 8; i++) {
        int m = m0 + tr * 8 + i;
        int n = n0 + tc * 8;
        float2 p0 = unpk(acc[i][0]), p1 = unpk(acc[i][1]);
        float2 p2 = unpk(acc[i][2]), p3 = unpk(acc[i][3]);
        float4 o0 = make_float4(p0.x + bias[n + 0], p0.y + bias[n + 1],
                                p1.x + bias[n + 2], p1.y + bias[n + 3]);
        float4 o1 = make_float4(p2.x + bias[n + 4], p2.y + bias[n + 5],
                                p3.x + bias[n + 6], p3.y + bias[n + 7]);
        *reinterpret_cast<float4*>(&C[(size_t)m * N + n])     = o0;
        *reinterpret_cast<float4*>(&C[(size_t)m * N + n + 4]) = o1;
    }
}

__global__ __launch_bounds__(256) void gemm_qkv_kernel(
    const float* __restrict__ x, const float* __restrict__ w, const float* __restrict__ b)
{
    gemm_bias_body<E3, EE>(x, w, b, g_qkv);
}

__global__ __launch_bounds__(256) void gemm_proj_kernel(
    const float* __restrict__ w, const float* __restrict__ b, float* __restrict__ out)
{
    gemm_bias_body<EE, EE>(g_attn, w, b, out);
}

// ---------------------------------------------------------------------------
// present[kv,b,h,n,d]: n<P from layer_past, n>=P from qkv (k at +E, v at +2E)
// ---------------------------------------------------------------------------
__global__ __launch_bounds__(256) void present_kernel(
    const float* __restrict__ past, float* __restrict__ present)
{
    int idx = blockIdx.x * 256 + threadIdx.x;   // float4 index
    int d4 = idx & 15;
    int t  = idx >> 4;
    int n  = t & (NSS - 1);  t >>= 11;
    int h  = t & (HH - 1);   t >>= 4;
    int b  = t & (BB - 1);
    int kv = t >> 2;

    float4 v;
    if (n < PP) {
        size_t src = ((((size_t)kv * BB + b) * HH + h) * PP + n) * 16 + d4;
        v = reinterpret_cast<const float4*>(past)[src];
    } else {
        int s = n - PP;
        v = *reinterpret_cast<const float4*>(
            &g_qkv[((size_t)(b * SS + s)) * E3 + (kv + 1) * EE + h * DD + d4 * 4]);
    }
    reinterpret_cast<float4*>(present)[idx] = v;
}

// ---------------------------------------------------------------------------
// Scores: S[bh,q,k] = (Q.K)/8, causal-masked to -10000.
// 128q x 128k tile, 256 threads, 8x8 microtile, BK=16 over D=64.
// ---------------------------------------------------------------------------
__global__ __launch_bounds__(256) void scores_kernel(const float* __restrict__ presentK)
{
    __shared__ float Qst[16][132];   // [d][q]
    __shared__ float Kst[16][132];   // [d][k]

    const int tid = threadIdx.x;
    const int kb  = blockIdx.x * 128;
    const int qb  = blockIdx.y * 128;
    const int bh  = blockIdx.z;
    const int b   = bh >> 4;
    const int h   = bh & 15;

    float* srow = g_scores + ((size_t)bh * SS + qb) * NSS + kb;

    if (kb > PP + qb + 127) {  // fully masked tile
        const float4 mneg = make_float4(-10000.f, -10000.f, -10000.f, -10000.f);
        for (int f = tid; f < 128 * 32; f += 256) {
            int r = f >> 5, c = (f & 31) * 4;
            *reinterpret_cast<float4*>(&srow[(size_t)r * NSS + c]) = mneg;
        }
        return;
    }

    const float* Q  = g_qkv + ((size_t)(b * SS + qb)) * E3 + h * DD;
    const float* Kp = presentK + ((size_t)bh * NSS + kb) * DD;

    const int tr = tid >> 4, tc = tid & 15;
    unsigned long long acc[8][4];
#pragma unroll
    for (int i = 0; i < 8; i++)
#pragma unroll
        for (int j = 0; j < 4; j++) acc[i][j] = 0ull;

    for (int d0 = 0; d0 < DD; d0 += 16) {
#pragma unroll
        for (int it = 0; it < 2; it++) {
            int f = tid + it * 256;          // 512 float4 = 128 rows x 4
            int row = f >> 2;
            int c4  = (f & 3) * 4;
            float4 v = *reinterpret_cast<const float4*>(&Q[(size_t)row * E3 + d0 + c4]);
            Qst[c4 + 0][row] = v.x; Qst[c4 + 1][row] = v.y;
            Qst[c4 + 2][row] = v.z; Qst[c4 + 3][row] = v.w;
        }
#pragma unroll
        for (int it = 0; it < 2; it++) {
            int f = tid + it * 256;
            int row = f >> 2;
            int c4  = (f & 3) * 4;
            float4 v = *reinterpret_cast<const float4*>(&Kp[(size_t)row * DD + d0 + c4]);
            Kst[c4 + 0][row] = v.x; Kst[c4 + 1][row] = v.y;
            Kst[c4 + 2][row] = v.z; Kst[c4 + 3][row] = v.w;
        }
        __syncthreads();

#pragma unroll
        for (int k = 0; k < 16; k++) {
            F4U a0, a1, b0, b1;
            a0.f = *reinterpret_cast<const float4*>(&Qst[k][tr * 8]);
            a1.f = *reinterpret_cast<const float4*>(&Qst[k][tr * 8 + 4]);
            b0.f = *reinterpret_cast<const float4*>(&Kst[k][tc * 8]);
            b1.f = *reinterpret_cast<const float4*>(&Kst[k][tc * 8 + 4]);
            float av[8] = {a0.f.x, a0.f.y, a0.f.z, a0.f.w,
                           a1.f.x, a1.f.y, a1.f.z, a1.f.w};
#pragma unroll
            for (int i = 0; i < 8; i++) {
                unsigned long long ai = dup2(av[i]);
                ffma2(acc[i][0], ai, b0.u[0]);
                ffma2(acc[i][1], ai, b0.u[1]);
                ffma2(acc[i][2], ai, b1.u[0]);
                ffma2(acc[i][3], ai, b1.u[1]);
            }
        }
        __syncthreads();
    }

    const bool full = (kb + 127 <= PP + qb);   // whole tile unmasked
    const float scale = 0.125f;
#pragma unroll
    for (int i = 0; i < 8; i++) {
        int q   = qb + tr * 8 + i;
        int lim = PP + q;
        int kc0 = kb + tc * 8;
        float v[8];
#pragma unroll
        for (int j = 0; j < 4; j++) {
            float2 p = unpk(acc[i][j]);
            v[j * 2 + 0] = p.x * scale;
            v[j * 2 + 1] = p.y * scale;
        }
        if (!full) {
#pragma unroll
            for (int j = 0; j < 8; j++)
                if (kc0 + j > lim) v[j] = -10000.f;
        }
        float4 o0 = make_float4(v[0], v[1], v[2], v[3]);
        float4 o1 = make_float4(v[4], v[5], v[6], v[7]);
        *reinterpret_cast<float4*>(&srow[(size_t)(tr * 8 + i) * NSS + tc * 8])     = o0;
        *reinterpret_cast<float4*>(&srow[(size_t)(tr * 8 + i) * NSS + tc * 8 + 4]) = o1;
    }
}

// ---------------------------------------------------------------------------
// Row softmax over 2048 elements (in place). 1 block = 1 row, 256 threads.
// ---------------------------------------------------------------------------
__global__ __launch_bounds__(256) void softmax_kernel()
{
    float* p = g_scores + (size_t)blockIdx.x * NSS;
    const int tid = threadIdx.x;

    float4 a = reinterpret_cast<const float4*>(p)[tid];
    float4 b = reinterpret_cast<const float4*>(p)[tid + 256];

    float m = fmaxf(fmaxf(fmaxf(a.x, a.y), fmaxf(a.z, a.w)),
                    fmaxf(fmaxf(b.x, b.y), fmaxf(b.z, b.w)));
#pragma unroll
    for (int o = 16; o; o >>= 1) m = fmaxf(m, __shfl_xor_sync(0xffffffffu, m, o));

    __shared__ float wmax[8];
    __shared__ float wsum[8];
    if ((tid & 31) == 0) wmax[tid >> 5] = m;
    __syncthreads();
    float mm = wmax[0];
#pragma unroll
    for (int i = 1; i < 8; i++) mm = fmaxf(mm, wmax[i]);

    a.x = __expf(a.x - mm); a.y = __expf(a.y - mm);
    a.z = __expf(a.z - mm); a.w = __expf(a.w - mm);
    b.x = __expf(b.x - mm); b.y = __expf(b.y - mm);
    b.z = __expf(b.z - mm); b.w = __expf(b.w - mm);

    float s = a.x + a.y + a.z + a.w + b.x + b.y + b.z + b.w;
#pragma unroll
    for (int o = 16; o; o >>= 1) s += __shfl_xor_sync(0xffffffffu, s, o);
    if ((tid & 31) == 0) wsum[tid >> 5] = s;
    __syncthreads();
    float ss = 0.f;
#pragma unroll
    for (int i = 0; i < 8; i++) ss += wsum[i];

    float r = 1.f / ss;
    a.x *= r; a.y *= r; a.z *= r; a.w *= r;
    b.x *= r; b.y *= r; b.z *= r; b.w *= r;
    reinterpret_cast<float4*>(p)[tid]       = a;
    reinterpret_cast<float4*>(p)[tid + 256] = b;
}

// ---------------------------------------------------------------------------
// PV: attn[b,q,h*64+d] = probs[bh,q,:] @ V[bh,:,d]
// 128q x 64d tile, 128 threads, 8x8 microtile, BK=32, causal k bound.
// ---------------------------------------------------------------------------
__global__ __launch_bounds__(128) void pv_kernel(const float* __restrict__ presentV)
{
    __shared__ float Pst[32][132];  // [k][q]
    __shared__ float Vs[32][68];    // [k][d]

    const int tid = threadIdx.x;
    const int qb  = blockIdx.x * 128;
    const int bh  = blockIdx.y;
    const int b   = bh >> 4;
    const int h   = bh & 15;

    const float* Prow = g_scores + ((size_t)bh * SS + qb) * NSS;
    const float* V    = presentV + (size_t)bh * NSS * DD;

    const int tr = tid >> 3;   // 0..15 (q groups of 8)
    const int tc = tid & 7;    // 0..7  (d groups of 8)

    unsigned long long acc[8][4];
#pragma unroll
    for (int i = 0; i < 8; i++)
#pragma unroll
        for (int j = 0; j < 4; j++) acc[i][j] = 0ull;

    const int kmax = PP + qb + 128;   // probs beyond are exactly 0

    for (int k0 = 0; k0 < kmax; k0 += 32) {
#pragma unroll
        for (int it = 0; it < 8; it++) {
            int f = tid + it * 128;        // 1024 float4 = 128 q-rows x 8
            int row = f >> 3;
            int c4  = (f & 7) * 4;
            float4 v = *reinterpret_cast<const float4*>(&Prow[(size_t)row * NSS + k0 + c4]);
            Pst[c4 + 0][row] = v.x; Pst[c4 + 1][row] = v.y;
            Pst[c4 + 2][row] = v.z; Pst[c4 + 3][row] = v.w;
        }
#pragma unroll
        for (int it = 0; it < 4; it++) {
            int f = tid + it * 128;        // 512 float4 = 32 k-rows x 16
            int row = f >> 4;
            int c4  = (f & 15) * 4;
            *reinterpret_cast<float4*>(&Vs[row][c4]) =
                *reinterpret_cast<const float4*>(&V[(size_t)(k0 + row) * DD + c4]);
        }
        __syncthreads();

#pragma unroll
        for (int k = 0; k < 32; k++) {
            F4U a0, a1, b0, b1;
            a0.f = *reinterpret_cast<const float4*>(&Pst[k][tr * 8]);
            a1.f = *reinterpret_cast<const float4*>(&Pst[k][tr * 8 + 4]);
            b0.f = *reinterpret_cast<const float4*>(&Vs[k][tc * 8]);
            b1.f = *reinterpret_cast<const float4*>(&Vs[k][tc * 8 + 4]);
            float av[8] = {a0.f.x, a0.f.y, a0.f.z, a0.f.w,
                           a1.f.x, a1.f.y, a1.f.z, a1.f.w};
#pragma unroll
            for (int i = 0; i < 8; i++) {
                unsigned long long ai = dup2(av[i]);
                ffma2(acc[i][0], ai, b0.u[0]);
                ffma2(acc[i][1], ai, b0.u[1]);
                ffma2(acc[i][2], ai, b1.u[0]);
                ffma2(acc[i][3], ai, b1.u[1]);
            }
        }
        __syncthreads();
    }

#pragma unroll
    for (int i = 0; i < 8; i++) {
        float2 p0 = unpk(acc[i][0]), p1 = unpk(acc[i][1]);
        float2 p2 = unpk(acc[i][2]), p3 = unpk(acc[i][3]);
        size_t off = ((size_t)(b * SS + qb + tr * 8 + i)) * EE + h * DD + tc * 8;
        *reinterpret_cast<float4*>(&g_attn[off])     = make_float4(p0.x, p0.y, p1.x, p1.y);
        *reinterpret_cast<float4*>(&g_attn[off + 4]) = make_float4(p2.x, p2.y, p3.x, p3.y);
    }
}

// ---------------------------------------------------------------------------
// Launch. Output layout: [ out (B*S*E) | present (2*B*H*NS*D) ]
// ---------------------------------------------------------------------------
extern "C" void kernel_launch(void* const* d_in, const int* in_sizes, int n_in,
                              void* d_out, int out_size)
{
    (void)in_sizes; (void)n_in; (void)out_size;
    const float* x      = (const float*)d_in[0];
    const float* past   = (const float*)d_in[1];
    const float* w_attn = (const float*)d_in[2];
    const float* b_attn = (const float*)d_in[3];
    const float* w_proj = (const float*)d_in[4];
    const float* b_proj = (const float*)d_in[5];

    float* out      = (float*)d_out;
    float* present  = out + (size_t)BB * SS * EE;
    float* presentK = present;
    float* presentV = present + (size_t)BB * HH * NSS * DD;

    // 1) QKV = x @ w_attn + b_attn
    gemm_qkv_kernel<<<dim3(E3 / 128, (BB * SS) / 128), 256>>>(x, w_attn, b_attn);

    // 2) present = concat(past, new K/V)
    {
        int n4 = 2 * BB * HH * NSS * (DD / 4);
        present_kernel<<<n4 / 256, 256>>>(past, present);
    }

    // 3) scores = mask(QK^T / sqrt(D))
    scores_kernel<<<dim3(NSS / 128, SS / 128, BB * HH), 256>>>(presentK);

    // 4) row softmax
    softmax_kernel<<<BB * HH * SS, 256>>>();

    // 5) attn = probs @ V
    pv_kernel<<<dim3(SS / 128, BB * HH), 128>>>(presentV);

    // 6) out = attn @ w_proj + b_proj
    gemm_proj_kernel<<<dim3(EE / 128, (BB * SS) / 128), 256>>>(w_proj, b_proj, out);
}

// round 6
// speedup vs baseline: 2.1883x; 2.1883x over previous
#include <cuda_runtime.h>
#include <cstdint>

// Problem constants
#define BB   4
#define SS   1024
#define EE   1024
#define HH   16
#define DD   64
#define PP   1024
#define NSS  2048          // P + S
#define E3   3072          // 3*E

// ---------------------------------------------------------------------------
// Scratch
// ---------------------------------------------------------------------------
__device__ float g_qkv[(size_t)BB * SS * E3];            // [B*S, 3E]
__device__ float g_scores[(size_t)BB * HH * SS * NSS];   // [B*H, S, NS]
__device__ float g_attn[(size_t)BB * SS * EE];           // [B*S, E]

// ---------------------------------------------------------------------------
// tf32 helpers
// ---------------------------------------------------------------------------
__device__ __forceinline__ float to_tf32(float x) {
    float r;
    asm("cvt.rna.tf32.f32 %0, %1;" : "=f"(r) : "f"(x));
    return r;
}

// D += A@B  (m16n8k8, A row-major, B col-major fragments, fp32 accum)
__device__ __forceinline__ void mma8(float* d, const uint32_t* a, const uint32_t* b) {
    asm("mma.sync.aligned.m16n8k8.row.col.f32.tf32.tf32.f32 "
        "{%0,%1,%2,%3}, {%4,%5,%6,%7}, {%8,%9}, {%0,%1,%2,%3};"
        : "+f"(d[0]), "+f"(d[1]), "+f"(d[2]), "+f"(d[3])
        : "r"(a[0]), "r"(a[1]), "r"(a[2]), "r"(a[3]), "r"(b[0]), "r"(b[1]));
}

__device__ __forceinline__ uint32_t fbits(float x) { return __float_as_uint(x); }

#define PAD_T 137   // transposed tiles (scalar STS): odd pad -> conflict-free stores
#define PAD_B 136   // vector-copied tiles: conflict-free fragment loads

// ---------------------------------------------------------------------------
// GEMM + bias: C[M,N] = A[M,K] @ B[K,N] + bias[N]   (tf32 MMA)
// Block 128x128, BK=32, 256 threads = 8 warps as 2(M) x 4(N), warp tile 64x32.
// ---------------------------------------------------------------------------
template<int N, int K>
__device__ __forceinline__ void mma_gemm_body(
    const float* __restrict__ A, const float* __restrict__ B,
    const float* __restrict__ bias, float* __restrict__ C)
{
    __shared__ float As[32][PAD_T];   // [k][m] transposed
    __shared__ float Bs[32][PAD_B];   // [k][n]

    const int tid  = threadIdx.x;
    const int lane = tid & 31;
    const int wid  = tid >> 5;
    const int wm   = (wid & 1) * 64;
    const int wn   = (wid >> 1) * 32;
    const int g    = lane >> 2;       // 0..7
    const int tg   = lane & 3;        // 0..3
    const int m0   = blockIdx.y * 128;
    const int n0   = blockIdx.x * 128;

    float acc[4][4][4];
#pragma unroll
    for (int mi = 0; mi < 4; mi++)
#pragma unroll
        for (int ni = 0; ni < 4; ni++)
#pragma unroll
            for (int j = 0; j < 4; j++) acc[mi][ni][j] = 0.f;

    for (int k0 = 0; k0 < K; k0 += 32) {
        // A tile 128x32 -> As[k][m] (tf32-rounded)
#pragma unroll
        for (int it = 0; it < 4; it++) {
            int f   = tid + it * 256;        // 1024 float4
            int row = f >> 3;                // 0..127
            int kq  = (f & 7) * 4;           // 0..28
            float4 v = *reinterpret_cast<const float4*>(&A[(size_t)(m0 + row) * K + k0 + kq]);
            As[kq + 0][row] = to_tf32(v.x); As[kq + 1][row] = to_tf32(v.y);
            As[kq + 2][row] = to_tf32(v.z); As[kq + 3][row] = to_tf32(v.w);
        }
        // B tile 32x128 -> Bs[k][n]
#pragma unroll
        for (int it = 0; it < 4; it++) {
            int f  = tid + it * 256;
            int kr = f >> 5;                 // 0..31
            int nc = (f & 31) * 4;           // 0..124
            float4 v = *reinterpret_cast<const float4*>(&B[(size_t)(k0 + kr) * N + n0 + nc]);
            float4 o = make_float4(to_tf32(v.x), to_tf32(v.y), to_tf32(v.z), to_tf32(v.w));
            *reinterpret_cast<float4*>(&Bs[kr][nc]) = o;
        }
        __syncthreads();

#pragma unroll
        for (int ks = 0; ks < 4; ks++) {
            const int k8 = ks * 8;
            uint32_t af[4][4], bf[4][2];
#pragma unroll
            for (int mi = 0; mi < 4; mi++) {
                int bm = wm + mi * 16;
                af[mi][0] = fbits(As[k8 + tg    ][bm + g    ]);
                af[mi][1] = fbits(As[k8 + tg    ][bm + g + 8]);
                af[mi][2] = fbits(As[k8 + tg + 4][bm + g    ]);
                af[mi][3] = fbits(As[k8 + tg + 4][bm + g + 8]);
            }
#pragma unroll
            for (int ni = 0; ni < 4; ni++) {
                int bn = wn + ni * 8;
                bf[ni][0] = fbits(Bs[k8 + tg    ][bn + g]);
                bf[ni][1] = fbits(Bs[k8 + tg + 4][bn + g]);
            }
#pragma unroll
            for (int mi = 0; mi < 4; mi++)
#pragma unroll
                for (int ni = 0; ni < 4; ni++)
                    mma8(acc[mi][ni], af[mi], bf[ni]);
        }
        __syncthreads();
    }

#pragma unroll
    for (int mi = 0; mi < 4; mi++)
#pragma unroll
        for (int ni = 0; ni < 4; ni++) {
            int r = m0 + wm + mi * 16 + g;
            int c = n0 + wn + ni * 8 + tg * 2;
            float b0 = bias[c], b1 = bias[c + 1];
            float2 o0 = make_float2(acc[mi][ni][0] + b0, acc[mi][ni][1] + b1);
            float2 o1 = make_float2(acc[mi][ni][2] + b0, acc[mi][ni][3] + b1);
            *reinterpret_cast<float2*>(&C[(size_t)r * N + c])       = o0;
            *reinterpret_cast<float2*>(&C[(size_t)(r + 8) * N + c]) = o1;
        }
}

__global__ __launch_bounds__(256) void gemm_qkv_kernel(
    const float* __restrict__ x, const float* __restrict__ w, const float* __restrict__ b)
{
    mma_gemm_body<E3, EE>(x, w, b, g_qkv);
}

__global__ __launch_bounds__(256) void gemm_proj_kernel(
    const float* __restrict__ w, const float* __restrict__ b, float* __restrict__ out)
{
    mma_gemm_body<EE, EE>(g_attn, w, b, out);
}

// ---------------------------------------------------------------------------
// present[kv,b,h,n,d]: n<P from layer_past, n>=P from qkv (k at +E, v at +2E)
// ---------------------------------------------------------------------------
__global__ __launch_bounds__(256) void present_kernel(
    const float* __restrict__ past, float* __restrict__ present)
{
    int idx = blockIdx.x * 256 + threadIdx.x;   // float4 index
    int d4 = idx & 15;
    int t  = idx >> 4;
    int n  = t & (NSS - 1);  t >>= 11;
    int h  = t & (HH - 1);   t >>= 4;
    int b  = t & (BB - 1);
    int kv = t >> 2;

    float4 v;
    if (n < PP) {
        size_t src = ((((size_t)kv * BB + b) * HH + h) * PP + n) * 16 + d4;
        v = reinterpret_cast<const float4*>(past)[src];
    } else {
        int s = n - PP;
        v = *reinterpret_cast<const float4*>(
            &g_qkv[((size_t)(b * SS + s)) * E3 + (kv + 1) * EE + h * DD + d4 * 4]);
    }
    reinterpret_cast<float4*>(present)[idx] = v;
}

// ---------------------------------------------------------------------------
// Scores: S[bh,q,k] = (Q.K)/8, causal-masked to -10000.  (tf32 MMA)
// Block 128q x 128k, 256 threads, warp tile 64x32, two passes over D=64.
// ---------------------------------------------------------------------------
__global__ __launch_bounds__(256) void scores_kernel(const float* __restrict__ presentK)
{
    __shared__ float Qs[32][PAD_T];   // [d][q]
    __shared__ float Ks[32][PAD_T];   // [d][k]

    const int tid  = threadIdx.x;
    const int lane = tid & 31;
    const int wid  = tid >> 5;
    const int wm   = (wid & 1) * 64;
    const int wn   = (wid >> 1) * 32;
    const int g    = lane >> 2;
    const int tg   = lane & 3;
    const int kb   = blockIdx.x * 128;
    const int qb   = blockIdx.y * 128;
    const int bh   = blockIdx.z;
    const int b    = bh >> 4;
    const int h    = bh & 15;

    float* srow = g_scores + ((size_t)bh * SS + qb) * NSS + kb;

    if (kb > PP + qb + 127) {  // fully masked tile
        const float4 mneg = make_float4(-10000.f, -10000.f, -10000.f, -10000.f);
        for (int f = tid; f < 128 * 32; f += 256) {
            int r = f >> 5, c = (f & 31) * 4;
            *reinterpret_cast<float4*>(&srow[(size_t)r * NSS + c]) = mneg;
        }
        return;
    }

    const float* Q  = g_qkv + ((size_t)(b * SS + qb)) * E3 + h * DD;
    const float* Kp = presentK + ((size_t)bh * NSS + kb) * DD;

    float acc[4][4][4];
#pragma unroll
    for (int mi = 0; mi < 4; mi++)
#pragma unroll
        for (int ni = 0; ni < 4; ni++)
#pragma unroll
            for (int j = 0; j < 4; j++) acc[mi][ni][j] = 0.f;

    for (int d0 = 0; d0 < DD; d0 += 32) {
#pragma unroll
        for (int it = 0; it < 4; it++) {
            int f   = tid + it * 256;
            int row = f >> 3;
            int c4  = (f & 7) * 4;
            float4 v = *reinterpret_cast<const float4*>(&Q[(size_t)row * E3 + d0 + c4]);
            Qs[c4 + 0][row] = to_tf32(v.x); Qs[c4 + 1][row] = to_tf32(v.y);
            Qs[c4 + 2][row] = to_tf32(v.z); Qs[c4 + 3][row] = to_tf32(v.w);
        }
#pragma unroll
        for (int it = 0; it < 4; it++) {
            int f   = tid + it * 256;
            int row = f >> 3;
            int c4  = (f & 7) * 4;
            float4 v = *reinterpret_cast<const float4*>(&Kp[(size_t)row * DD + d0 + c4]);
            Ks[c4 + 0][row] = to_tf32(v.x); Ks[c4 + 1][row] = to_tf32(v.y);
            Ks[c4 + 2][row] = to_tf32(v.z); Ks[c4 + 3][row] = to_tf32(v.w);
        }
        __syncthreads();

#pragma unroll
        for (int ks = 0; ks < 4; ks++) {
            const int k8 = ks * 8;
            uint32_t af[4][4], bf[4][2];
#pragma unroll
            for (int mi = 0; mi < 4; mi++) {
                int bm = wm + mi * 16;
                af[mi][0] = fbits(Qs[k8 + tg    ][bm + g    ]);
                af[mi][1] = fbits(Qs[k8 + tg    ][bm + g + 8]);
                af[mi][2] = fbits(Qs[k8 + tg + 4][bm + g    ]);
                af[mi][3] = fbits(Qs[k8 + tg + 4][bm + g + 8]);
            }
#pragma unroll
            for (int ni = 0; ni < 4; ni++) {
                int bn = wn + ni * 8;
                bf[ni][0] = fbits(Ks[k8 + tg    ][bn + g]);
                bf[ni][1] = fbits(Ks[k8 + tg + 4][bn + g]);
            }
#pragma unroll
            for (int mi = 0; mi < 4; mi++)
#pragma unroll
                for (int ni = 0; ni < 4; ni++)
                    mma8(acc[mi][ni], af[mi], bf[ni]);
        }
        __syncthreads();
    }

    const bool full = (kb + 127 <= PP + qb);
    const float scale = 0.125f;
#pragma unroll
    for (int mi = 0; mi < 4; mi++)
#pragma unroll
        for (int ni = 0; ni < 4; ni++) {
            int rq = wm + mi * 16 + g;          // local q row
            int q0 = qb + rq;
            int kc = kb + wn + ni * 8 + tg * 2;
            float v0 = acc[mi][ni][0] * scale;
            float v1 = acc[mi][ni][1] * scale;
            float v2 = acc[mi][ni][2] * scale;
            float v3 = acc[mi][ni][3] * scale;
            if (!full) {
                if (kc     > PP + q0)     v0 = -10000.f;
                if (kc + 1 > PP + q0)     v1 = -10000.f;
                if (kc     > PP + q0 + 8) v2 = -10000.f;
                if (kc + 1 > PP + q0 + 8) v3 = -10000.f;
            }
            int cl = wn + ni * 8 + tg * 2;
            *reinterpret_cast<float2*>(&srow[(size_t)rq * NSS + cl])       = make_float2(v0, v1);
            *reinterpret_cast<float2*>(&srow[(size_t)(rq + 8) * NSS + cl]) = make_float2(v2, v3);
        }
}

// ---------------------------------------------------------------------------
// Row softmax over 2048 elements (in place). 1 block = 1 row, 256 threads.
// ---------------------------------------------------------------------------
__global__ __launch_bounds__(256) void softmax_kernel()
{
    float* p = g_scores + (size_t)blockIdx.x * NSS;
    const int tid = threadIdx.x;

    float4 a = reinterpret_cast<const float4*>(p)[tid];
    float4 b = reinterpret_cast<const float4*>(p)[tid + 256];

    float m = fmaxf(fmaxf(fmaxf(a.x, a.y), fmaxf(a.z, a.w)),
                    fmaxf(fmaxf(b.x, b.y), fmaxf(b.z, b.w)));
#pragma unroll
    for (int o = 16; o; o >>= 1) m = fmaxf(m, __shfl_xor_sync(0xffffffffu, m, o));

    __shared__ float wmax[8];
    __shared__ float wsum[8];
    if ((tid & 31) == 0) wmax[tid >> 5] = m;
    __syncthreads();
    float mm = wmax[0];
#pragma unroll
    for (int i = 1; i < 8; i++) mm = fmaxf(mm, wmax[i]);

    a.x = __expf(a.x - mm); a.y = __expf(a.y - mm);
    a.z = __expf(a.z - mm); a.w = __expf(a.w - mm);
    b.x = __expf(b.x - mm); b.y = __expf(b.y - mm);
    b.z = __expf(b.z - mm); b.w = __expf(b.w - mm);

    float s = a.x + a.y + a.z + a.w + b.x + b.y + b.z + b.w;
#pragma unroll
    for (int o = 16; o; o >>= 1) s += __shfl_xor_sync(0xffffffffu, s, o);
    if ((tid & 31) == 0) wsum[tid >> 5] = s;
    __syncthreads();
    float ss = 0.f;
#pragma unroll
    for (int i = 0; i < 8; i++) ss += wsum[i];

    float r = 1.f / ss;
    a.x *= r; a.y *= r; a.z *= r; a.w *= r;
    b.x *= r; b.y *= r; b.z *= r; b.w *= r;
    reinterpret_cast<float4*>(p)[tid]       = a;
    reinterpret_cast<float4*>(p)[tid + 256] = b;
}

// ---------------------------------------------------------------------------
// PV: attn[b,q,h*64+d] = probs[bh,q,:] @ V[bh,:,d]   (tf32 MMA)
// Block 128q x 64d, 128 threads = 4 warps as 2(M) x 2(N), warp tile 64x32.
// ---------------------------------------------------------------------------
__global__ __launch_bounds__(128) void pv_kernel(const float* __restrict__ presentV)
{
    __shared__ float Ps[32][PAD_T];   // [k][q]
    __shared__ float Vs[32][72];      // [k][d]

    const int tid  = threadIdx.x;
    const int lane = tid & 31;
    const int wid  = tid >> 5;
    const int wm   = (wid & 1) * 64;
    const int wn   = (wid >> 1) * 32;
    const int g    = lane >> 2;
    const int tg   = lane & 3;
    const int qb   = blockIdx.x * 128;
    const int bh   = blockIdx.y;
    const int b    = bh >> 4;
    const int h    = bh & 15;

    const float* Prow = g_scores + ((size_t)bh * SS + qb) * NSS;
    const float* V    = presentV + (size_t)bh * NSS * DD;

    float acc[4][4][4];
#pragma unroll
    for (int mi = 0; mi < 4; mi++)
#pragma unroll
        for (int ni = 0; ni < 4; ni++)
#pragma unroll
            for (int j = 0; j < 4; j++) acc[mi][ni][j] = 0.f;

    const int kmax = PP + qb + 128;   // probs beyond are exactly 0

    for (int k0 = 0; k0 < kmax; k0 += 32) {
#pragma unroll
        for (int it = 0; it < 8; it++) {
            int f   = tid + it * 128;        // 1024 float4
            int row = f >> 3;                // q row 0..127
            int c4  = (f & 7) * 4;
            float4 v = *reinterpret_cast<const float4*>(&Prow[(size_t)row * NSS + k0 + c4]);
            Ps[c4 + 0][row] = to_tf32(v.x); Ps[c4 + 1][row] = to_tf32(v.y);
            Ps[c4 + 2][row] = to_tf32(v.z); Ps[c4 + 3][row] = to_tf32(v.w);
        }
#pragma unroll
        for (int it = 0; it < 4; it++) {
            int f   = tid + it * 128;        // 512 float4 = 32 rows x 16
            int row = f >> 4;
            int c4  = (f & 15) * 4;
            float4 v = *reinterpret_cast<const float4*>(&V[(size_t)(k0 + row) * DD + c4]);
            float4 o = make_float4(to_tf32(v.x), to_tf32(v.y), to_tf32(v.z), to_tf32(v.w));
            *reinterpret_cast<float4*>(&Vs[row][c4]) = o;
        }
        __syncthreads();

#pragma unroll
        for (int ks = 0; ks < 4; ks++) {
            const int k8 = ks * 8;
            uint32_t af[4][4], bf[4][2];
#pragma unroll
            for (int mi = 0; mi < 4; mi++) {
                int bm = wm + mi * 16;
                af[mi][0] = fbits(Ps[k8 + tg    ][bm + g    ]);
                af[mi][1] = fbits(Ps[k8 + tg    ][bm + g + 8]);
                af[mi][2] = fbits(Ps[k8 + tg + 4][bm + g    ]);
                af[mi][3] = fbits(Ps[k8 + tg + 4][bm + g + 8]);
            }
#pragma unroll
            for (int ni = 0; ni < 4; ni++) {
                int bn = wn + ni * 8;
                bf[ni][0] = fbits(Vs[k8 + tg    ][bn + g]);
                bf[ni][1] = fbits(Vs[k8 + tg + 4][bn + g]);
            }
#pragma unroll
            for (int mi = 0; mi < 4; mi++)
#pragma unroll
                for (int ni = 0; ni < 4; ni++)
                    mma8(acc[mi][ni], af[mi], bf[ni]);
        }
        __syncthreads();
    }

#pragma unroll
    for (int mi = 0; mi < 4; mi++)
#pragma unroll
        for (int ni = 0; ni < 4; ni++) {
            int q  = qb + wm + mi * 16 + g;
            int dc = wn + ni * 8 + tg * 2;
            size_t off = ((size_t)(b * SS + q)) * EE + h * DD + dc;
            *reinterpret_cast<float2*>(&g_attn[off]) =
                make_float2(acc[mi][ni][0], acc[mi][ni][1]);
            *reinterpret_cast<float2*>(&g_attn[off + (size_t)8 * EE]) =
                make_float2(acc[mi][ni][2], acc[mi][ni][3]);
        }
}

// ---------------------------------------------------------------------------
// Launch. Output layout: [ out (B*S*E) | present (2*B*H*NS*D) ]
// ---------------------------------------------------------------------------
extern "C" void kernel_launch(void* const* d_in, const int* in_sizes, int n_in,
                              void* d_out, int out_size)
{
    (void)in_sizes; (void)n_in; (void)out_size;
    const float* x      = (const float*)d_in[0];
    const float* past   = (const float*)d_in[1];
    const float* w_attn = (const float*)d_in[2];
    const float* b_attn = (const float*)d_in[3];
    const float* w_proj = (const float*)d_in[4];
    const float* b_proj = (const float*)d_in[5];

    float* out      = (float*)d_out;
    float* present  = out + (size_t)BB * SS * EE;
    float* presentK = present;
    float* presentV = present + (size_t)BB * HH * NSS * DD;

    // 1) QKV = x @ w_attn + b_attn
    gemm_qkv_kernel<<<dim3(E3 / 128, (BB * SS) / 128), 256>>>(x, w_attn, b_attn);

    // 2) present = concat(past, new K/V)
    {
        int n4 = 2 * BB * HH * NSS * (DD / 4);
        present_kernel<<<n4 / 256, 256>>>(past, present);
    }

    // 3) scores = mask(QK^T / sqrt(D))
    scores_kernel<<<dim3(NSS / 128, SS / 128, BB * HH), 256>>>(presentK);

    // 4) row softmax
    softmax_kernel<<<BB * HH * SS, 256>>>();

    // 5) attn = probs @ V
    pv_kernel<<<dim3(SS / 128, BB * HH), 128>>>(presentV);

    // 6) out = attn @ w_proj + b_proj
    gemm_proj_kernel<<<dim3(EE / 128, (BB * SS) / 128), 256>>>(w_proj, b_proj, out);
}

// round 7
// speedup vs baseline: 3.0524x; 1.3949x over previous
#include <cuda_runtime.h>
#include <cstdint>

// Problem constants
#define BB   4
#define SS   1024
#define EE   1024
#define HH   16
#define DD   64
#define PP   1024
#define NSS  2048          // P + S
#define E3   3072          // 3*E

// ---------------------------------------------------------------------------
// Scratch
// ---------------------------------------------------------------------------
__device__ float g_qkv[(size_t)BB * SS * E3];            // [B*S, 3E]
__device__ float g_attn[(size_t)BB * SS * EE];           // [B*S, E]

// ---------------------------------------------------------------------------
// tf32 helpers
// ---------------------------------------------------------------------------
__device__ __forceinline__ float to_tf32(float x) {
    float r;
    asm("cvt.rna.tf32.f32 %0, %1;" : "=f"(r) : "f"(x));
    return r;
}

// D += A@B  (m16n8k8, A row-major, B col-major fragments, fp32 accum)
__device__ __forceinline__ void mma8(float* d, const uint32_t* a, const uint32_t* b) {
    asm("mma.sync.aligned.m16n8k8.row.col.f32.tf32.tf32.f32 "
        "{%0,%1,%2,%3}, {%4,%5,%6,%7}, {%8,%9}, {%0,%1,%2,%3};"
        : "+f"(d[0]), "+f"(d[1]), "+f"(d[2]), "+f"(d[3])
        : "r"(a[0]), "r"(a[1]), "r"(a[2]), "r"(a[3]), "r"(b[0]), "r"(b[1]));
}

__device__ __forceinline__ uint32_t fbits(float x) { return __float_as_uint(x); }

#define PAD_T 137
#define PAD_B 136

// ---------------------------------------------------------------------------
// GEMM + bias: C[M,N] = A[M,K] @ B[K,N] + bias[N]   (tf32 MMA)
// Block 128x128, BK=32, 256 threads = 8 warps as 2(M) x 4(N), warp tile 64x32.
// ---------------------------------------------------------------------------
template<int N, int K>
__device__ __forceinline__ void mma_gemm_body(
    const float* __restrict__ A, const float* __restrict__ B,
    const float* __restrict__ bias, float* __restrict__ C)
{
    __shared__ float As[32][PAD_T];   // [k][m] transposed
    __shared__ float Bs[32][PAD_B];   // [k][n]

    const int tid  = threadIdx.x;
    const int lane = tid & 31;
    const int wid  = tid >> 5;
    const int wm   = (wid & 1) * 64;
    const int wn   = (wid >> 1) * 32;
    const int g    = lane >> 2;
    const int tg   = lane & 3;
    const int m0   = blockIdx.y * 128;
    const int n0   = blockIdx.x * 128;

    float acc[4][4][4];
#pragma unroll
    for (int mi = 0; mi < 4; mi++)
#pragma unroll
        for (int ni = 0; ni < 4; ni++)
#pragma unroll
            for (int j = 0; j < 4; j++) acc[mi][ni][j] = 0.f;

    for (int k0 = 0; k0 < K; k0 += 32) {
#pragma unroll
        for (int it = 0; it < 4; it++) {
            int f   = tid + it * 256;
            int row = f >> 3;
            int kq  = (f & 7) * 4;
            float4 v = *reinterpret_cast<const float4*>(&A[(size_t)(m0 + row) * K + k0 + kq]);
            As[kq + 0][row] = to_tf32(v.x); As[kq + 1][row] = to_tf32(v.y);
            As[kq + 2][row] = to_tf32(v.z); As[kq + 3][row] = to_tf32(v.w);
        }
#pragma unroll
        for (int it = 0; it < 4; it++) {
            int f  = tid + it * 256;
            int kr = f >> 5;
            int nc = (f & 31) * 4;
            float4 v = *reinterpret_cast<const float4*>(&B[(size_t)(k0 + kr) * N + n0 + nc]);
            float4 o = make_float4(to_tf32(v.x), to_tf32(v.y), to_tf32(v.z), to_tf32(v.w));
            *reinterpret_cast<float4*>(&Bs[kr][nc]) = o;
        }
        __syncthreads();

#pragma unroll
        for (int ks = 0; ks < 4; ks++) {
            const int k8 = ks * 8;
            uint32_t af[4][4], bf[4][2];
#pragma unroll
            for (int mi = 0; mi < 4; mi++) {
                int bm = wm + mi * 16;
                af[mi][0] = fbits(As[k8 + tg    ][bm + g    ]);
                af[mi][1] = fbits(As[k8 + tg    ][bm + g + 8]);
                af[mi][2] = fbits(As[k8 + tg + 4][bm + g    ]);
                af[mi][3] = fbits(As[k8 + tg + 4][bm + g + 8]);
            }
#pragma unroll
            for (int ni = 0; ni < 4; ni++) {
                int bn = wn + ni * 8;
                bf[ni][0] = fbits(Bs[k8 + tg    ][bn + g]);
                bf[ni][1] = fbits(Bs[k8 + tg + 4][bn + g]);
            }
#pragma unroll
            for (int mi = 0; mi < 4; mi++)
#pragma unroll
                for (int ni = 0; ni < 4; ni++)
                    mma8(acc[mi][ni], af[mi], bf[ni]);
        }
        __syncthreads();
    }

#pragma unroll
    for (int mi = 0; mi < 4; mi++)
#pragma unroll
        for (int ni = 0; ni < 4; ni++) {
            int r = m0 + wm + mi * 16 + g;
            int c = n0 + wn + ni * 8 + tg * 2;
            float b0 = bias[c], b1 = bias[c + 1];
            float2 o0 = make_float2(acc[mi][ni][0] + b0, acc[mi][ni][1] + b1);
            float2 o1 = make_float2(acc[mi][ni][2] + b0, acc[mi][ni][3] + b1);
            *reinterpret_cast<float2*>(&C[(size_t)r * N + c])       = o0;
            *reinterpret_cast<float2*>(&C[(size_t)(r + 8) * N + c]) = o1;
        }
}

__global__ __launch_bounds__(256) void gemm_qkv_kernel(
    const float* __restrict__ x, const float* __restrict__ w, const float* __restrict__ b)
{
    mma_gemm_body<E3, EE>(x, w, b, g_qkv);
}

__global__ __launch_bounds__(256) void gemm_proj_kernel(
    const float* __restrict__ w, const float* __restrict__ b, float* __restrict__ out)
{
    mma_gemm_body<EE, EE>(g_attn, w, b, out);
}

// ---------------------------------------------------------------------------
// present[kv,b,h,n,d]: n<P from layer_past, n>=P from qkv (k at +E, v at +2E)
// ---------------------------------------------------------------------------
__global__ __launch_bounds__(256) void present_kernel(
    const float* __restrict__ past, float* __restrict__ present)
{
    int idx = blockIdx.x * 256 + threadIdx.x;   // float4 index
    int d4 = idx & 15;
    int t  = idx >> 4;
    int n  = t & (NSS - 1);  t >>= 11;
    int h  = t & (HH - 1);   t >>= 4;
    int b  = t & (BB - 1);
    int kv = t >> 2;

    float4 v;
    if (n < PP) {
        size_t src = ((((size_t)kv * BB + b) * HH + h) * PP + n) * 16 + d4;
        v = reinterpret_cast<const float4*>(past)[src];
    } else {
        int s = n - PP;
        v = *reinterpret_cast<const float4*>(
            &g_qkv[((size_t)(b * SS + s)) * E3 + (kv + 1) * EE + h * DD + d4 * 4]);
    }
    reinterpret_cast<float4*>(present)[idx] = v;
}

// ---------------------------------------------------------------------------
// Fused flash attention: scores (tf32 MMA) -> online softmax (regs) -> PV (tf32 MMA)
// Block = 128 q-rows x full head; 256 threads = 8 warps, each warp owns 16 q-rows.
// K/V streamed in 64-seq tiles through smem; P never leaves the warp (shfl
// transform C-frag -> A-frag). Writes merged-head attn to g_attn.
// ---------------------------------------------------------------------------
__global__ __launch_bounds__(256) void flash_kernel(
    const float* __restrict__ presentK, const float* __restrict__ presentV)
{
    __shared__ union SMem {
        struct { float Ks[64][72]; float Vs[64][72]; } kv;  // natural [seq][d]
        float Qs[128][72];                                   // natural [q][d]
    } sm;

    const int tid  = threadIdx.x;
    const int lane = tid & 31;
    const int wid  = tid >> 5;
    const int wm   = wid * 16;          // warp's q-row base (0..112)
    const int g    = lane >> 2;         // 0..7
    const int tg   = lane & 3;          // 0..3
    const int qb   = blockIdx.x * 128;
    const int bh   = blockIdx.y;
    const int b    = bh >> 4;
    const int h    = bh & 15;

    const float* Q  = g_qkv + ((size_t)(b * SS + qb)) * E3 + h * DD;
    const float* Kp = presentK + (size_t)bh * NSS * DD;
    const float* Vp = presentV + (size_t)bh * NSS * DD;

    // ---- Prologue: stage Q tile, pull A-fragments into registers ----
#pragma unroll
    for (int it = 0; it < 8; it++) {
        int f   = tid + it * 256;
        int row = f >> 4;
        int c4  = (f & 15) * 4;
        float4 v = *reinterpret_cast<const float4*>(&Q[(size_t)row * E3 + c4]);
        sm.Qs[row][c4 + 0] = to_tf32(v.x); sm.Qs[row][c4 + 1] = to_tf32(v.y);
        sm.Qs[row][c4 + 2] = to_tf32(v.z); sm.Qs[row][c4 + 3] = to_tf32(v.w);
    }
    __syncthreads();

    uint32_t qf[8][4];
#pragma unroll
    for (int d8 = 0; d8 < 8; d8++) {
        qf[d8][0] = fbits(sm.Qs[wm + g    ][d8 * 8 + tg    ]);
        qf[d8][1] = fbits(sm.Qs[wm + g + 8][d8 * 8 + tg    ]);
        qf[d8][2] = fbits(sm.Qs[wm + g    ][d8 * 8 + tg + 4]);
        qf[d8][3] = fbits(sm.Qs[wm + g + 8][d8 * 8 + tg + 4]);
    }
    __syncthreads();

    // ---- Online softmax state + O accumulator ----
    float m_lo = -1e30f, m_hi = -1e30f, l_lo = 0.f, l_hi = 0.f;
    float o[8][4];
#pragma unroll
    for (int nd = 0; nd < 8; nd++)
#pragma unroll
        for (int j = 0; j < 4; j++) o[nd][j] = 0.f;

    const int q_lo = qb + wm + g;       // this thread's low q-row
    const int nt   = (PP + qb) / 64 + 2;
    const int diag0 = (PP + qb) / 64;   // first diagonal tile index

    for (int t = 0; t < nt; t++) {
        const int kb = t * 64;
        __syncthreads();   // previous iteration's smem consumers done

        // Load K, V 64x64 tiles (coalesced, tf32-rounded)
#pragma unroll
        for (int it = 0; it < 4; it++) {
            int f   = tid + it * 256;
            int row = f >> 4;
            int c4  = (f & 15) * 4;
            float4 v = *reinterpret_cast<const float4*>(&Kp[(size_t)(kb + row) * DD + c4]);
            sm.kv.Ks[row][c4 + 0] = to_tf32(v.x); sm.kv.Ks[row][c4 + 1] = to_tf32(v.y);
            sm.kv.Ks[row][c4 + 2] = to_tf32(v.z); sm.kv.Ks[row][c4 + 3] = to_tf32(v.w);
        }
#pragma unroll
        for (int it = 0; it < 4; it++) {
            int f   = tid + it * 256;
            int row = f >> 4;
            int c4  = (f & 15) * 4;
            float4 v = *reinterpret_cast<const float4*>(&Vp[(size_t)(kb + row) * DD + c4]);
            sm.kv.Vs[row][c4 + 0] = to_tf32(v.x); sm.kv.Vs[row][c4 + 1] = to_tf32(v.y);
            sm.kv.Vs[row][c4 + 2] = to_tf32(v.z); sm.kv.Vs[row][c4 + 3] = to_tf32(v.w);
        }
        __syncthreads();

        // ---- S = Q @ K^T  (per warp: 16 x 64) ----
        float s[8][4];
#pragma unroll
        for (int ni = 0; ni < 8; ni++) {
            s[ni][0] = 0.f; s[ni][1] = 0.f; s[ni][2] = 0.f; s[ni][3] = 0.f;
#pragma unroll
            for (int d8 = 0; d8 < 8; d8++) {
                uint32_t bf[2];
                bf[0] = fbits(sm.kv.Ks[ni * 8 + g][d8 * 8 + tg    ]);
                bf[1] = fbits(sm.kv.Ks[ni * 8 + g][d8 * 8 + tg + 4]);
                mma8(s[ni], qf[d8], bf);
            }
        }

        // scale + causal mask (exactly -10000 like the reference)
        const bool diag = (t >= diag0);
#pragma unroll
        for (int ni = 0; ni < 8; ni++) {
            s[ni][0] *= 0.125f; s[ni][1] *= 0.125f;
            s[ni][2] *= 0.125f; s[ni][3] *= 0.125f;
            if (diag) {
                int kc = kb + ni * 8 + tg * 2;
                if (kc     > PP + q_lo)     s[ni][0] = -10000.f;
                if (kc + 1 > PP + q_lo)     s[ni][1] = -10000.f;
                if (kc     > PP + q_lo + 8) s[ni][2] = -10000.f;
                if (kc + 1 > PP + q_lo + 8) s[ni][3] = -10000.f;
            }
        }

        // ---- row max (reduce over ni, then over tg-quad) ----
        float tl = -1e30f, th = -1e30f;
#pragma unroll
        for (int ni = 0; ni < 8; ni++) {
            tl = fmaxf(tl, fmaxf(s[ni][0], s[ni][1]));
            th = fmaxf(th, fmaxf(s[ni][2], s[ni][3]));
        }
        tl = fmaxf(tl, __shfl_xor_sync(0xffffffffu, tl, 1));
        tl = fmaxf(tl, __shfl_xor_sync(0xffffffffu, tl, 2));
        th = fmaxf(th, __shfl_xor_sync(0xffffffffu, th, 1));
        th = fmaxf(th, __shfl_xor_sync(0xffffffffu, th, 2));

        float mn_lo = fmaxf(m_lo, tl);
        float mn_hi = fmaxf(m_hi, th);
        float al = __expf(m_lo - mn_lo);
        float ah = __expf(m_hi - mn_hi);

        // ---- exp + row sum ----
        float sl = 0.f, sh = 0.f;
#pragma unroll
        for (int ni = 0; ni < 8; ni++) {
            s[ni][0] = __expf(s[ni][0] - mn_lo);
            s[ni][1] = __expf(s[ni][1] - mn_lo);
            s[ni][2] = __expf(s[ni][2] - mn_hi);
            s[ni][3] = __expf(s[ni][3] - mn_hi);
            sl += s[ni][0] + s[ni][1];
            sh += s[ni][2] + s[ni][3];
        }
        sl += __shfl_xor_sync(0xffffffffu, sl, 1);
        sl += __shfl_xor_sync(0xffffffffu, sl, 2);
        sh += __shfl_xor_sync(0xffffffffu, sh, 1);
        sh += __shfl_xor_sync(0xffffffffu, sh, 2);

        l_lo = l_lo * al + sl;
        l_hi = l_hi * ah + sh;
        m_lo = mn_lo;
        m_hi = mn_hi;

        // ---- rescale O ----
#pragma unroll
        for (int nd = 0; nd < 8; nd++) {
            o[nd][0] *= al; o[nd][1] *= al;
            o[nd][2] *= ah; o[nd][3] *= ah;
        }

        // ---- PV: O += P @ V ----
        const int src0 = (lane & ~3) | (tg >> 1);
        const int src2 = src0 + 2;
        const bool odd = tg & 1;
#pragma unroll
        for (int j = 0; j < 8; j++) {
            // C-frag -> A-frag shuffle transform of P block j (seq cols 8j..8j+7)
            float e0 = __shfl_sync(0xffffffffu, s[j][0], src0);
            float e1 = __shfl_sync(0xffffffffu, s[j][1], src0);
            float e2 = __shfl_sync(0xffffffffu, s[j][2], src0);
            float e3 = __shfl_sync(0xffffffffu, s[j][3], src0);
            float f0 = __shfl_sync(0xffffffffu, s[j][0], src2);
            float f1 = __shfl_sync(0xffffffffu, s[j][1], src2);
            float f2 = __shfl_sync(0xffffffffu, s[j][2], src2);
            float f3 = __shfl_sync(0xffffffffu, s[j][3], src2);
            uint32_t pa[4];
            pa[0] = fbits(to_tf32(odd ? e1 : e0));
            pa[1] = fbits(to_tf32(odd ? e3 : e2));
            pa[2] = fbits(to_tf32(odd ? f1 : f0));
            pa[3] = fbits(to_tf32(odd ? f3 : f2));
#pragma unroll
            for (int nd = 0; nd < 8; nd++) {
                uint32_t bf[2];
                bf[0] = fbits(sm.kv.Vs[j * 8 + tg    ][nd * 8 + g]);
                bf[1] = fbits(sm.kv.Vs[j * 8 + tg + 4][nd * 8 + g]);
                mma8(o[nd], pa, bf);
            }
        }
    }

    // ---- Epilogue: normalize, write merged-head attn ----
    float il_lo = 1.f / l_lo;
    float il_hi = 1.f / l_hi;
#pragma unroll
    for (int nd = 0; nd < 8; nd++) {
        int dc = nd * 8 + tg * 2;
        size_t off = ((size_t)(b * SS + q_lo)) * EE + h * DD + dc;
        *reinterpret_cast<float2*>(&g_attn[off]) =
            make_float2(o[nd][0] * il_lo, o[nd][1] * il_lo);
        *reinterpret_cast<float2*>(&g_attn[off + (size_t)8 * EE]) =
            make_float2(o[nd][2] * il_hi, o[nd][3] * il_hi);
    }
}

// ---------------------------------------------------------------------------
// Launch. Output layout: [ out (B*S*E) | present (2*B*H*NS*D) ]
// ---------------------------------------------------------------------------
extern "C" void kernel_launch(void* const* d_in, const int* in_sizes, int n_in,
                              void* d_out, int out_size)
{
    (void)in_sizes; (void)n_in; (void)out_size;
    const float* x      = (const float*)d_in[0];
    const float* past   = (const float*)d_in[1];
    const float* w_attn = (const float*)d_in[2];
    const float* b_attn = (const float*)d_in[3];
    const float* w_proj = (const float*)d_in[4];
    const float* b_proj = (const float*)d_in[5];

    float* out      = (float*)d_out;
    float* present  = out + (size_t)BB * SS * EE;
    float* presentK = present;
    float* presentV = present + (size_t)BB * HH * NSS * DD;

    // 1) QKV = x @ w_attn + b_attn
    gemm_qkv_kernel<<<dim3(E3 / 128, (BB * SS) / 128), 256>>>(x, w_attn, b_attn);

    // 2) present = concat(past, new K/V)
    {
        int n4 = 2 * BB * HH * NSS * (DD / 4);
        present_kernel<<<n4 / 256, 256>>>(past, present);
    }

    // 3) fused scores + softmax + PV
    flash_kernel<<<dim3(SS / 128, BB * HH), 256>>>(presentK, presentV);

    // 4) out = attn @ w_proj + b_proj
    gemm_proj_kernel<<<dim3(EE / 128, (BB * SS) / 128), 256>>>(w_proj, b_proj, out);
}

// round 10
// speedup vs baseline: 3.2800x; 1.0746x over previous
#include <cuda_runtime.h>
#include <cstdint>

// Problem constants
#define BB   4
#define SS   1024
#define EE   1024
#define HH   16
#define DD   64
#define PP   1024
#define NSS  2048          // P + S
#define E3   3072          // 3*E

// ---------------------------------------------------------------------------
// Scratch
// ---------------------------------------------------------------------------
__device__ float g_qkv[(size_t)BB * SS * E3];            // [B*S, 3E]
__device__ float g_attn[(size_t)BB * SS * EE];           // [B*S, E]

// ---------------------------------------------------------------------------
// tf32 / cp.async helpers
// ---------------------------------------------------------------------------
__device__ __forceinline__ float to_tf32(float x) {
    float r;
    asm("cvt.rna.tf32.f32 %0, %1;" : "=f"(r) : "f"(x));
    return r;
}

// D += A@B  (m16n8k8, A row-major, B col-major fragments, fp32 accum)
__device__ __forceinline__ void mma8(float* d, const uint32_t* a, const uint32_t* b) {
    asm("mma.sync.aligned.m16n8k8.row.col.f32.tf32.tf32.f32 "
        "{%0,%1,%2,%3}, {%4,%5,%6,%7}, {%8,%9}, {%0,%1,%2,%3};"
        : "+f"(d[0]), "+f"(d[1]), "+f"(d[2]), "+f"(d[3])
        : "r"(a[0]), "r"(a[1]), "r"(a[2]), "r"(a[3]), "r"(b[0]), "r"(b[1]));
}

__device__ __forceinline__ uint32_t fbits(float x) { return __float_as_uint(x); }

__device__ __forceinline__ void cp16(void* sdst, const void* gsrc) {
    uint32_t s = (uint32_t)__cvta_generic_to_shared(sdst);
    asm volatile("cp.async.cg.shared.global [%0], [%1], 16;" :: "r"(s), "l"(gsrc));
}
#define CP_COMMIT() asm volatile("cp.async.commit_group;")
#define CP_WAIT1()  asm volatile("cp.async.wait_group 1;")

// GEMM smem geometry (floats)
#define A_LDA  36                       // 32 + 4 pad: frag banks 4g+tg, conflict-free
#define B_LDB  136                      // 128 + 8 pad: frag banks 8tg+g, conflict-free
#define A_SZ   (128 * A_LDA)            // 4608
#define B_SZ   (32 * B_LDB)             // 4352
#define STG_SZ (A_SZ + B_SZ)            // 8960 floats per stage
#define GEMM_SMEM_BYTES (2 * STG_SZ * 4) // 71680 B

// ---------------------------------------------------------------------------
// GEMM + bias: C[M,N] = A[M,K] @ B[K,N] + bias[N]   (tf32 MMA)
// Block 128x128, BK=32, 256 threads = 8 warps as 2(M) x 4(N), warp tile 64x32.
// 2-stage cp.async pipeline. NOTE: cp.async groups are per-thread; a
// __syncthreads() AFTER wait_group is required before reading other threads'
// copies (this was the R7 bug).
// ---------------------------------------------------------------------------
template<int N, int K>
__device__ __forceinline__ void mma_gemm_body(
    const float* __restrict__ A, const float* __restrict__ B,
    const float* __restrict__ bias, float* __restrict__ C)
{
    extern __shared__ float sm[];

    const int tid  = threadIdx.x;
    const int lane = tid & 31;
    const int wid  = tid >> 5;
    const int wm   = (wid & 1) * 64;
    const int wn   = (wid >> 1) * 32;
    const int g    = lane >> 2;       // 0..7
    const int tg   = lane & 3;        // 0..3
    const int m0   = blockIdx.y * 128;
    const int n0   = blockIdx.x * 128;

    float acc[4][4][4];
#pragma unroll
    for (int mi = 0; mi < 4; mi++)
#pragma unroll
        for (int ni = 0; ni < 4; ni++)
#pragma unroll
            for (int j = 0; j < 4; j++) acc[mi][ni][j] = 0.f;

    auto copy_tile = [&](int stage, int k0) {
        float* As = sm + stage * STG_SZ;
        float* Bs = As + A_SZ;
#pragma unroll
        for (int it = 0; it < 4; it++) {
            int f   = tid + it * 256;        // 1024 float4 chunks: 128 rows x 8
            int row = f >> 3;
            int kq  = (f & 7) * 4;
            cp16(&As[row * A_LDA + kq], &A[(size_t)(m0 + row) * K + k0 + kq]);
        }
#pragma unroll
        for (int it = 0; it < 4; it++) {
            int f  = tid + it * 256;         // 1024 chunks: 32 rows x 32
            int kr = f >> 5;
            int nc = (f & 31) * 4;
            cp16(&Bs[kr * B_LDB + nc], &B[(size_t)(k0 + kr) * N + n0 + nc]);
        }
    };

    const int nt = K / 32;
    copy_tile(0, 0);
    CP_COMMIT();

    for (int i = 0; i < nt; i++) {
        __syncthreads();                     // all reads of stage (i+1)&1 done
        if (i + 1 < nt) copy_tile((i + 1) & 1, (i + 1) * 32);
        CP_COMMIT();
        CP_WAIT1();                          // own copies for tile i complete
        __syncthreads();                     // ALL threads' copies visible

        const float* As = sm + (i & 1) * STG_SZ;
        const float* Bs = As + A_SZ;

#pragma unroll
        for (int ks = 0; ks < 4; ks++) {
            const int k8 = ks * 8;
            uint32_t af[4][4], bf[4][2];
#pragma unroll
            for (int mi = 0; mi < 4; mi++) {
                const float* ar0 = &As[(wm + mi * 16 + g) * A_LDA + k8 + tg];
                const float* ar1 = ar0 + 8 * A_LDA;
                af[mi][0] = fbits(to_tf32(ar0[0]));
                af[mi][1] = fbits(to_tf32(ar1[0]));
                af[mi][2] = fbits(to_tf32(ar0[4]));
                af[mi][3] = fbits(to_tf32(ar1[4]));
            }
#pragma unroll
            for (int ni = 0; ni < 4; ni++) {
                int bn = wn + ni * 8 + g;
                bf[ni][0] = fbits(to_tf32(Bs[(k8 + tg) * B_LDB + bn]));
                bf[ni][1] = fbits(to_tf32(Bs[(k8 + tg + 4) * B_LDB + bn]));
            }
#pragma unroll
            for (int mi = 0; mi < 4; mi++)
#pragma unroll
                for (int ni = 0; ni < 4; ni++)
                    mma8(acc[mi][ni], af[mi], bf[ni]);
        }
    }

#pragma unroll
    for (int mi = 0; mi < 4; mi++)
#pragma unroll
        for (int ni = 0; ni < 4; ni++) {
            int r = m0 + wm + mi * 16 + g;
            int c = n0 + wn + ni * 8 + tg * 2;
            float b0 = bias[c], b1 = bias[c + 1];
            float2 o0 = make_float2(acc[mi][ni][0] + b0, acc[mi][ni][1] + b1);
            float2 o1 = make_float2(acc[mi][ni][2] + b0, acc[mi][ni][3] + b1);
            *reinterpret_cast<float2*>(&C[(size_t)r * N + c])       = o0;
            *reinterpret_cast<float2*>(&C[(size_t)(r + 8) * N + c]) = o1;
        }
}

__global__ __launch_bounds__(256, 2) void gemm_qkv_kernel(
    const float* __restrict__ x, const float* __restrict__ w, const float* __restrict__ b)
{
    mma_gemm_body<E3, EE>(x, w, b, g_qkv);
}

__global__ __launch_bounds__(256, 2) void gemm_proj_kernel(
    const float* __restrict__ w, const float* __restrict__ b, float* __restrict__ out)
{
    mma_gemm_body<EE, EE>(g_attn, w, b, out);
}

// ---------------------------------------------------------------------------
// present[kv,b,h,n,d]: n<P from layer_past, n>=P from qkv (k at +E, v at +2E)
// ---------------------------------------------------------------------------
__global__ __launch_bounds__(256) void present_kernel(
    const float* __restrict__ past, float* __restrict__ present)
{
    int idx = blockIdx.x * 256 + threadIdx.x;   // float4 index
    int d4 = idx & 15;
    int t  = idx >> 4;
    int n  = t & (NSS - 1);  t >>= 11;
    int h  = t & (HH - 1);   t >>= 4;
    int b  = t & (BB - 1);
    int kv = t >> 2;

    float4 v;
    if (n < PP) {
        size_t src = ((((size_t)kv * BB + b) * HH + h) * PP + n) * 16 + d4;
        v = reinterpret_cast<const float4*>(past)[src];
    } else {
        int s = n - PP;
        v = *reinterpret_cast<const float4*>(
            &g_qkv[((size_t)(b * SS + s)) * E3 + (kv + 1) * EE + h * DD + d4 * 4]);
    }
    reinterpret_cast<float4*>(present)[idx] = v;
}

// ---------------------------------------------------------------------------
// Fused flash attention: scores (tf32 MMA) -> online softmax (regs) -> PV (tf32 MMA)
// Block = 128 q-rows x full head; 256 threads = 8 warps, each warp owns 16 q-rows.
// ---------------------------------------------------------------------------
__global__ __launch_bounds__(256) void flash_kernel(
    const float* __restrict__ presentK, const float* __restrict__ presentV)
{
    __shared__ union SMem {
        struct { float Ks[64][72]; float Vs[64][72]; } kv;  // natural [seq][d]
        float Qs[128][72];                                   // natural [q][d]
    } sm;

    const int tid  = threadIdx.x;
    const int lane = tid & 31;
    const int wid  = tid >> 5;
    const int wm   = wid * 16;          // warp's q-row base (0..112)
    const int g    = lane >> 2;         // 0..7
    const int tg   = lane & 3;          // 0..3
    const int qb   = blockIdx.x * 128;
    const int bh   = blockIdx.y;
    const int b    = bh >> 4;
    const int h    = bh & 15;

    const float* Q  = g_qkv + ((size_t)(b * SS + qb)) * E3 + h * DD;
    const float* Kp = presentK + (size_t)bh * NSS * DD;
    const float* Vp = presentV + (size_t)bh * NSS * DD;

    // ---- Prologue: stage Q tile, pull A-fragments into registers ----
#pragma unroll
    for (int it = 0; it < 8; it++) {
        int f   = tid + it * 256;
        int row = f >> 4;
        int c4  = (f & 15) * 4;
        float4 v = *reinterpret_cast<const float4*>(&Q[(size_t)row * E3 + c4]);
        sm.Qs[row][c4 + 0] = to_tf32(v.x); sm.Qs[row][c4 + 1] = to_tf32(v.y);
        sm.Qs[row][c4 + 2] = to_tf32(v.z); sm.Qs[row][c4 + 3] = to_tf32(v.w);
    }
    __syncthreads();

    uint32_t qf[8][4];
#pragma unroll
    for (int d8 = 0; d8 < 8; d8++) {
        qf[d8][0] = fbits(sm.Qs[wm + g    ][d8 * 8 + tg    ]);
        qf[d8][1] = fbits(sm.Qs[wm + g + 8][d8 * 8 + tg    ]);
        qf[d8][2] = fbits(sm.Qs[wm + g    ][d8 * 8 + tg + 4]);
        qf[d8][3] = fbits(sm.Qs[wm + g + 8][d8 * 8 + tg + 4]);
    }
    __syncthreads();

    // ---- Online softmax state + O accumulator ----
    float m_lo = -1e30f, m_hi = -1e30f, l_lo = 0.f, l_hi = 0.f;
    float o[8][4];
#pragma unroll
    for (int nd = 0; nd < 8; nd++)
#pragma unroll
        for (int j = 0; j < 4; j++) o[nd][j] = 0.f;

    const int q_lo = qb + wm + g;       // this thread's low q-row
    const int nt   = (PP + qb) / 64 + 2;
    const int diag0 = (PP + qb) / 64;   // first diagonal tile index

    for (int t = 0; t < nt; t++) {
        const int kb = t * 64;
        __syncthreads();   // previous iteration's smem consumers done

        // Load K, V 64x64 tiles (coalesced, tf32-rounded)
#pragma unroll
        for (int it = 0; it < 4; it++) {
            int f   = tid + it * 256;
            int row = f >> 4;
            int c4  = (f & 15) * 4;
            float4 v = *reinterpret_cast<const float4*>(&Kp[(size_t)(kb + row) * DD + c4]);
            sm.kv.Ks[row][c4 + 0] = to_tf32(v.x); sm.kv.Ks[row][c4 + 1] = to_tf32(v.y);
            sm.kv.Ks[row][c4 + 2] = to_tf32(v.z); sm.kv.Ks[row][c4 + 3] = to_tf32(v.w);
        }
#pragma unroll
        for (int it = 0; it < 4; it++) {
            int f   = tid + it * 256;
            int row = f >> 4;
            int c4  = (f & 15) * 4;
            float4 v = *reinterpret_cast<const float4*>(&Vp[(size_t)(kb + row) * DD + c4]);
            sm.kv.Vs[row][c4 + 0] = to_tf32(v.x); sm.kv.Vs[row][c4 + 1] = to_tf32(v.y);
            sm.kv.Vs[row][c4 + 2] = to_tf32(v.z); sm.kv.Vs[row][c4 + 3] = to_tf32(v.w);
        }
        __syncthreads();

        // ---- S = Q @ K^T  (per warp: 16 x 64) ----
        float s[8][4];
#pragma unroll
        for (int ni = 0; ni < 8; ni++) {
            s[ni][0] = 0.f; s[ni][1] = 0.f; s[ni][2] = 0.f; s[ni][3] = 0.f;
#pragma unroll
            for (int d8 = 0; d8 < 8; d8++) {
                uint32_t bf[2];
                bf[0] = fbits(sm.kv.Ks[ni * 8 + g][d8 * 8 + tg    ]);
                bf[1] = fbits(sm.kv.Ks[ni * 8 + g][d8 * 8 + tg + 4]);
                mma8(s[ni], qf[d8], bf);
            }
        }

        // scale + causal mask (exactly -10000 like the reference)
        const bool diag = (t >= diag0);
#pragma unroll
        for (int ni = 0; ni < 8; ni++) {
            s[ni][0] *= 0.125f; s[ni][1] *= 0.125f;
            s[ni][2] *= 0.125f; s[ni][3] *= 0.125f;
            if (diag) {
                int kc = kb + ni * 8 + tg * 2;
                if (kc     > PP + q_lo)     s[ni][0] = -10000.f;
                if (kc + 1 > PP + q_lo)     s[ni][1] = -10000.f;
                if (kc     > PP + q_lo + 8) s[ni][2] = -10000.f;
                if (kc + 1 > PP + q_lo + 8) s[ni][3] = -10000.f;
            }
        }

        // ---- row max (reduce over ni, then over tg-quad) ----
        float tl = -1e30f, th = -1e30f;
#pragma unroll
        for (int ni = 0; ni < 8; ni++) {
            tl = fmaxf(tl, fmaxf(s[ni][0], s[ni][1]));
            th = fmaxf(th, fmaxf(s[ni][2], s[ni][3]));
        }
        tl = fmaxf(tl, __shfl_xor_sync(0xffffffffu, tl, 1));
        tl = fmaxf(tl, __shfl_xor_sync(0xffffffffu, tl, 2));
        th = fmaxf(th, __shfl_xor_sync(0xffffffffu, th, 1));
        th = fmaxf(th, __shfl_xor_sync(0xffffffffu, th, 2));

        float mn_lo = fmaxf(m_lo, tl);
        float mn_hi = fmaxf(m_hi, th);
        float al = __expf(m_lo - mn_lo);
        float ah = __expf(m_hi - mn_hi);

        // ---- exp + row sum ----
        float sl = 0.f, sh = 0.f;
#pragma unroll
        for (int ni = 0; ni < 8; ni++) {
            s[ni][0] = __expf(s[ni][0] - mn_lo);
            s[ni][1] = __expf(s[ni][1] - mn_lo);
            s[ni][2] = __expf(s[ni][2] - mn_hi);
            s[ni][3] = __expf(s[ni][3] - mn_hi);
            sl += s[ni][0] + s[ni][1];
            sh += s[ni][2] + s[ni][3];
        }
        sl += __shfl_xor_sync(0xffffffffu, sl, 1);
        sl += __shfl_xor_sync(0xffffffffu, sl, 2);
        sh += __shfl_xor_sync(0xffffffffu, sh, 1);
        sh += __shfl_xor_sync(0xffffffffu, sh, 2);

        l_lo = l_lo * al + sl;
        l_hi = l_hi * ah + sh;
        m_lo = mn_lo;
        m_hi = mn_hi;

        // ---- rescale O ----
#pragma unroll
        for (int nd = 0; nd < 8; nd++) {
            o[nd][0] *= al; o[nd][1] *= al;
            o[nd][2] *= ah; o[nd][3] *= ah;
        }

        // ---- PV: O += P @ V ----
        const int src0 = (lane & ~3) | (tg >> 1);
        const int src2 = src0 + 2;
        const bool odd = tg & 1;
#pragma unroll
        for (int j = 0; j < 8; j++) {
            float e0 = __shfl_sync(0xffffffffu, s[j][0], src0);
            float e1 = __shfl_sync(0xffffffffu, s[j][1], src0);
            float e2 = __shfl_sync(0xffffffffu, s[j][2], src0);
            float e3 = __shfl_sync(0xffffffffu, s[j][3], src0);
            float f0 = __shfl_sync(0xffffffffu, s[j][0], src2);
            float f1 = __shfl_sync(0xffffffffu, s[j][1], src2);
            float f2 = __shfl_sync(0xffffffffu, s[j][2], src2);
            float f3 = __shfl_sync(0xffffffffu, s[j][3], src2);
            uint32_t pa[4];
            pa[0] = fbits(to_tf32(odd ? e1 : e0));
            pa[1] = fbits(to_tf32(odd ? e3 : e2));
            pa[2] = fbits(to_tf32(odd ? f1 : f0));
            pa[3] = fbits(to_tf32(odd ? f3 : f2));
#pragma unroll
            for (int nd = 0; nd < 8; nd++) {
                uint32_t bf[2];
                bf[0] = fbits(sm.kv.Vs[j * 8 + tg    ][nd * 8 + g]);
                bf[1] = fbits(sm.kv.Vs[j * 8 + tg + 4][nd * 8 + g]);
                mma8(o[nd], pa, bf);
            }
        }
    }

    // ---- Epilogue: normalize, write merged-head attn ----
    float il_lo = 1.f / l_lo;
    float il_hi = 1.f / l_hi;
#pragma unroll
    for (int nd = 0; nd < 8; nd++) {
        int dc = nd * 8 + tg * 2;
        size_t off = ((size_t)(b * SS + q_lo)) * EE + h * DD + dc;
        *reinterpret_cast<float2*>(&g_attn[off]) =
            make_float2(o[nd][0] * il_lo, o[nd][1] * il_lo);
        *reinterpret_cast<float2*>(&g_attn[off + (size_t)8 * EE]) =
            make_float2(o[nd][2] * il_hi, o[nd][3] * il_hi);
    }
}

// ---------------------------------------------------------------------------
// Launch. Output layout: [ out (B*S*E) | present (2*B*H*NS*D) ]
// ---------------------------------------------------------------------------
extern "C" void kernel_launch(void* const* d_in, const int* in_sizes, int n_in,
                              void* d_out, int out_size)
{
    (void)in_sizes; (void)n_in; (void)out_size;
    const float* x      = (const float*)d_in[0];
    const float* past   = (const float*)d_in[1];
    const float* w_attn = (const float*)d_in[2];
    const float* b_attn = (const float*)d_in[3];
    const float* w_proj = (const float*)d_in[4];
    const float* b_proj = (const float*)d_in[5];

    float* out      = (float*)d_out;
    float* present  = out + (size_t)BB * SS * EE;
    float* presentK = present;
    float* presentV = present + (size_t)BB * HH * NSS * DD;

    // Opt-in to 70KB dynamic smem (idempotent, not stream-ordered; safe under capture)
    cudaFuncSetAttribute(gemm_qkv_kernel,
                         cudaFuncAttributeMaxDynamicSharedMemorySize, GEMM_SMEM_BYTES);
    cudaFuncSetAttribute(gemm_proj_kernel,
                         cudaFuncAttributeMaxDynamicSharedMemorySize, GEMM_SMEM_BYTES);

    // 1) QKV = x @ w_attn + b_attn
    gemm_qkv_kernel<<<dim3(E3 / 128, (BB * SS) / 128), 256, GEMM_SMEM_BYTES>>>(x, w_attn, b_attn);

    // 2) present = concat(past, new K/V)
    {
        int n4 = 2 * BB * HH * NSS * (DD / 4);
        present_kernel<<<n4 / 256, 256>>>(past, present);
    }

    // 3) fused scores + softmax + PV
    flash_kernel<<<dim3(SS / 128, BB * HH), 256>>>(presentK, presentV);

    // 4) out = attn @ w_proj + b_proj
    gemm_proj_kernel<<<dim3(EE / 128, (BB * SS) / 128), 256, GEMM_SMEM_BYTES>>>(w_proj, b_proj, out);
}

// round 12
// speedup vs baseline: 3.3178x; 1.0115x over previous
#include <cuda_runtime.h>
#include <cstdint>

// Problem constants
#define BB   4
#define SS   1024
#define EE   1024
#define HH   16
#define DD   64
#define PP   1024
#define NSS  2048          // P + S
#define E3   3072          // 3*E

// ---------------------------------------------------------------------------
// Scratch
// ---------------------------------------------------------------------------
__device__ float g_qkv[(size_t)BB * SS * E3];            // [B*S, 3E]
__device__ float g_attn[(size_t)BB * SS * EE];           // [B*S, E]

// ---------------------------------------------------------------------------
// tf32 / cp.async helpers
// ---------------------------------------------------------------------------
__device__ __forceinline__ float to_tf32(float x) {
    float r;
    asm("cvt.rna.tf32.f32 %0, %1;" : "=f"(r) : "f"(x));
    return r;
}

// D += A@B  (m16n8k8, A row-major, B col-major fragments, fp32 accum)
__device__ __forceinline__ void mma8(float* d, const uint32_t* a, const uint32_t* b) {
    asm("mma.sync.aligned.m16n8k8.row.col.f32.tf32.tf32.f32 "
        "{%0,%1,%2,%3}, {%4,%5,%6,%7}, {%8,%9}, {%0,%1,%2,%3};"
        : "+f"(d[0]), "+f"(d[1]), "+f"(d[2]), "+f"(d[3])
        : "r"(a[0]), "r"(a[1]), "r"(a[2]), "r"(a[3]), "r"(b[0]), "r"(b[1]));
}

__device__ __forceinline__ uint32_t fbits(float x) { return __float_as_uint(x); }

__device__ __forceinline__ void cp16(void* sdst, const void* gsrc) {
    uint32_t s = (uint32_t)__cvta_generic_to_shared(sdst);
    asm volatile("cp.async.cg.shared.global [%0], [%1], 16;" :: "r"(s), "l"(gsrc));
}
#define CP_COMMIT() asm volatile("cp.async.commit_group;")
#define CP_WAIT1()  asm volatile("cp.async.wait_group 1;")

// GEMM smem geometry (floats)
#define A_LDA  36                       // 32 + 4 pad: frag banks 4g+tg, conflict-free
#define B_LDB  136                      // 128 + 8 pad: frag banks 8tg+g, conflict-free
#define A_SZ   (128 * A_LDA)            // 4608
#define B_SZ   (32 * B_LDB)             // 4352
#define STG_SZ (A_SZ + B_SZ)            // 8960 floats per stage
#define GEMM_SMEM_BYTES (2 * STG_SZ * 4) // 71680 B

// Flash smem geometry (floats)
#define F_LD     72                       // K/V row stride (conflict-free, R6-verified)
#define F_KV     (64 * F_LD)              // 4608 floats per K or V tile
#define F_STG    (2 * F_KV)               // 9216 floats per stage (K+V)
#define FLASH_SMEM_BYTES (2 * F_STG * 4)  // 73728 B (Q prologue reuses stage 0)

// ---------------------------------------------------------------------------
// GEMM + bias: C[M,N] = A[M,K] @ B[K,N] + bias[N]   (tf32 MMA)
// Block 128x128, BK=32, 256 threads = 8 warps as 2(M) x 4(N), warp tile 64x32.
// 2-stage cp.async pipeline (wait_group THEN __syncthreads — per-thread groups).
// ---------------------------------------------------------------------------
template<int N, int K>
__device__ __forceinline__ void mma_gemm_body(
    const float* __restrict__ A, const float* __restrict__ B,
    const float* __restrict__ bias, float* __restrict__ C)
{
    extern __shared__ float sm[];

    const int tid  = threadIdx.x;
    const int lane = tid & 31;
    const int wid  = tid >> 5;
    const int wm   = (wid & 1) * 64;
    const int wn   = (wid >> 1) * 32;
    const int g    = lane >> 2;       // 0..7
    const int tg   = lane & 3;        // 0..3
    const int m0   = blockIdx.y * 128;
    const int n0   = blockIdx.x * 128;

    float acc[4][4][4];
#pragma unroll
    for (int mi = 0; mi < 4; mi++)
#pragma unroll
        for (int ni = 0; ni < 4; ni++)
#pragma unroll
            for (int j = 0; j < 4; j++) acc[mi][ni][j] = 0.f;

    auto copy_tile = [&](int stage, int k0) {
        float* As = sm + stage * STG_SZ;
        float* Bs = As + A_SZ;
#pragma unroll
        for (int it = 0; it < 4; it++) {
            int f   = tid + it * 256;        // 1024 float4 chunks: 128 rows x 8
            int row = f >> 3;
            int kq  = (f & 7) * 4;
            cp16(&As[row * A_LDA + kq], &A[(size_t)(m0 + row) * K + k0 + kq]);
        }
#pragma unroll
        for (int it = 0; it < 4; it++) {
            int f  = tid + it * 256;         // 1024 chunks: 32 rows x 32
            int kr = f >> 5;
            int nc = (f & 31) * 4;
            cp16(&Bs[kr * B_LDB + nc], &B[(size_t)(k0 + kr) * N + n0 + nc]);
        }
    };

    const int nt = K / 32;
    copy_tile(0, 0);
    CP_COMMIT();

    for (int i = 0; i < nt; i++) {
        __syncthreads();                     // all reads of stage (i+1)&1 done
        if (i + 1 < nt) copy_tile((i + 1) & 1, (i + 1) * 32);
        CP_COMMIT();
        CP_WAIT1();                          // own copies for tile i complete
        __syncthreads();                     // ALL threads' copies visible

        const float* As = sm + (i & 1) * STG_SZ;
        const float* Bs = As + A_SZ;

#pragma unroll
        for (int ks = 0; ks < 4; ks++) {
            const int k8 = ks * 8;
            uint32_t af[4][4], bf[4][2];
#pragma unroll
            for (int mi = 0; mi < 4; mi++) {
                const float* ar0 = &As[(wm + mi * 16 + g) * A_LDA + k8 + tg];
                const float* ar1 = ar0 + 8 * A_LDA;
                af[mi][0] = fbits(to_tf32(ar0[0]));
                af[mi][1] = fbits(to_tf32(ar1[0]));
                af[mi][2] = fbits(to_tf32(ar0[4]));
                af[mi][3] = fbits(to_tf32(ar1[4]));
            }
#pragma unroll
            for (int ni = 0; ni < 4; ni++) {
                int bn = wn + ni * 8 + g;
                bf[ni][0] = fbits(to_tf32(Bs[(k8 + tg) * B_LDB + bn]));
                bf[ni][1] = fbits(to_tf32(Bs[(k8 + tg + 4) * B_LDB + bn]));
            }
#pragma unroll
            for (int mi = 0; mi < 4; mi++)
#pragma unroll
                for (int ni = 0; ni < 4; ni++)
                    mma8(acc[mi][ni], af[mi], bf[ni]);
        }
    }

#pragma unroll
    for (int mi = 0; mi < 4; mi++)
#pragma unroll
        for (int ni = 0; ni < 4; ni++) {
            int r = m0 + wm + mi * 16 + g;
            int c = n0 + wn + ni * 8 + tg * 2;
            float b0 = bias[c], b1 = bias[c + 1];
            float2 o0 = make_float2(acc[mi][ni][0] + b0, acc[mi][ni][1] + b1);
            float2 o1 = make_float2(acc[mi][ni][2] + b0, acc[mi][ni][3] + b1);
            *reinterpret_cast<float2*>(&C[(size_t)r * N + c])       = o0;
            *reinterpret_cast<float2*>(&C[(size_t)(r + 8) * N + c]) = o1;
        }
}

__global__ __launch_bounds__(256, 2) void gemm_qkv_kernel(
    const float* __restrict__ x, const float* __restrict__ w, const float* __restrict__ b)
{
    mma_gemm_body<E3, EE>(x, w, b, g_qkv);
}

__global__ __launch_bounds__(256, 2) void gemm_proj_kernel(
    const float* __restrict__ w, const float* __restrict__ b, float* __restrict__ out)
{
    mma_gemm_body<EE, EE>(g_attn, w, b, out);
}

// ---------------------------------------------------------------------------
// present[kv,b,h,n,d]: n<P from layer_past, n>=P from qkv (k at +E, v at +2E)
// ---------------------------------------------------------------------------
__global__ __launch_bounds__(256) void present_kernel(
    const float* __restrict__ past, float* __restrict__ present)
{
    int idx = blockIdx.x * 256 + threadIdx.x;   // float4 index
    int d4 = idx & 15;
    int t  = idx >> 4;
    int n  = t & (NSS - 1);  t >>= 11;
    int h  = t & (HH - 1);   t >>= 4;
    int b  = t & (BB - 1);
    int kv = t >> 2;

    float4 v;
    if (n < PP) {
        size_t src = ((((size_t)kv * BB + b) * HH + h) * PP + n) * 16 + d4;
        v = reinterpret_cast<const float4*>(past)[src];
    } else {
        int s = n - PP;
        v = *reinterpret_cast<const float4*>(
            &g_qkv[((size_t)(b * SS + s)) * E3 + (kv + 1) * EE + h * DD + d4 * 4]);
    }
    reinterpret_cast<float4*>(present)[idx] = v;
}

// ---------------------------------------------------------------------------
// Fused flash attention: scores (tf32 MMA) -> online softmax (regs) -> PV (tf32 MMA)
// Block = 128 q-rows x full head; 256 threads = 8 warps, each warp owns 16 q-rows.
// K/V streamed via 2-stage cp.async pipeline; tf32 cvt at fragment-build time
// (same RNA rounding on the same values as before => identical arithmetic).
// ---------------------------------------------------------------------------
__global__ __launch_bounds__(256) void flash_kernel(
    const float* __restrict__ presentK, const float* __restrict__ presentV)
{
    extern __shared__ float smf[];   // [2][ K(64x72) | V(64x72) ]; Q prologue uses stage 0

    const int tid  = threadIdx.x;
    const int lane = tid & 31;
    const int wid  = tid >> 5;
    const int wm   = wid * 16;          // warp's q-row base (0..112)
    const int g    = lane >> 2;         // 0..7
    const int tg   = lane & 3;          // 0..3
    const int qb   = blockIdx.x * 128;
    const int bh   = blockIdx.y;
    const int b    = bh >> 4;
    const int h    = bh & 15;

    const float* Q  = g_qkv + ((size_t)(b * SS + qb)) * E3 + h * DD;
    const float* Kp = presentK + (size_t)bh * NSS * DD;
    const float* Vp = presentV + (size_t)bh * NSS * DD;

    // ---- Prologue: stage Q tile (128x72 = exactly stage 0), build A-fragments ----
#pragma unroll
    for (int it = 0; it < 8; it++) {
        int f   = tid + it * 256;
        int row = f >> 4;
        int c4  = (f & 15) * 4;
        float4 v = *reinterpret_cast<const float4*>(&Q[(size_t)row * E3 + c4]);
        float* qrow = &smf[row * F_LD];
        qrow[c4 + 0] = to_tf32(v.x); qrow[c4 + 1] = to_tf32(v.y);
        qrow[c4 + 2] = to_tf32(v.z); qrow[c4 + 3] = to_tf32(v.w);
    }
    __syncthreads();

    uint32_t qf[8][4];
#pragma unroll
    for (int d8 = 0; d8 < 8; d8++) {
        qf[d8][0] = fbits(smf[(wm + g    ) * F_LD + d8 * 8 + tg    ]);
        qf[d8][1] = fbits(smf[(wm + g + 8) * F_LD + d8 * 8 + tg    ]);
        qf[d8][2] = fbits(smf[(wm + g    ) * F_LD + d8 * 8 + tg + 4]);
        qf[d8][3] = fbits(smf[(wm + g + 8) * F_LD + d8 * 8 + tg + 4]);
    }
    __syncthreads();   // stage 0 free for K/V

    auto copy_kv = [&](int stage, int kb) {
        float* Ks = smf + stage * F_STG;
        float* Vs = Ks + F_KV;
#pragma unroll
        for (int it = 0; it < 4; it++) {
            int f   = tid + it * 256;        // 1024 chunks: 64 rows x 16
            int row = f >> 4;
            int c4  = (f & 15) * 4;
            cp16(&Ks[row * F_LD + c4], &Kp[(size_t)(kb + row) * DD + c4]);
        }
#pragma unroll
        for (int it = 0; it < 4; it++) {
            int f   = tid + it * 256;
            int row = f >> 4;
            int c4  = (f & 15) * 4;
            cp16(&Vs[row * F_LD + c4], &Vp[(size_t)(kb + row) * DD + c4]);
        }
    };

    // ---- Online softmax state + O accumulator ----
    float m_lo = -1e30f, m_hi = -1e30f, l_lo = 0.f, l_hi = 0.f;
    float o[8][4];
#pragma unroll
    for (int nd = 0; nd < 8; nd++)
#pragma unroll
        for (int j = 0; j < 4; j++) o[nd][j] = 0.f;

    const int q_lo = qb + wm + g;       // this thread's low q-row
    const int nt   = (PP + qb) / 64 + 2;
    const int diag0 = (PP + qb) / 64;   // first diagonal tile index

    copy_kv(0, 0);
    CP_COMMIT();

    for (int t = 0; t < nt; t++) {
        const int kb = t * 64;
        __syncthreads();                 // all reads of stage (t+1)&1 done
        if (t + 1 < nt) copy_kv((t + 1) & 1, (t + 1) * 64);
        CP_COMMIT();
        CP_WAIT1();                      // own copies for tile t complete
        __syncthreads();                 // ALL threads' copies visible

        const float* Ks = smf + (t & 1) * F_STG;
        const float* Vs = Ks + F_KV;

        // ---- S = Q @ K^T  (per warp: 16 x 64) ----
        float s[8][4];
#pragma unroll
        for (int ni = 0; ni < 8; ni++) {
            s[ni][0] = 0.f; s[ni][1] = 0.f; s[ni][2] = 0.f; s[ni][3] = 0.f;
            const float* krow = &Ks[(ni * 8 + g) * F_LD];
#pragma unroll
            for (int d8 = 0; d8 < 8; d8++) {
                uint32_t bf[2];
                bf[0] = fbits(to_tf32(krow[d8 * 8 + tg    ]));
                bf[1] = fbits(to_tf32(krow[d8 * 8 + tg + 4]));
                mma8(s[ni], qf[d8], bf);
            }
        }

        // scale + causal mask (exactly -10000 like the reference)
        const bool diag = (t >= diag0);
#pragma unroll
        for (int ni = 0; ni < 8; ni++) {
            s[ni][0] *= 0.125f; s[ni][1] *= 0.125f;
            s[ni][2] *= 0.125f; s[ni][3] *= 0.125f;
            if (diag) {
                int kc = kb + ni * 8 + tg * 2;
                if (kc     > PP + q_lo)     s[ni][0] = -10000.f;
                if (kc + 1 > PP + q_lo)     s[ni][1] = -10000.f;
                if (kc     > PP + q_lo + 8) s[ni][2] = -10000.f;
                if (kc + 1 > PP + q_lo + 8) s[ni][3] = -10000.f;
            }
        }

        // ---- row max (reduce over ni, then over tg-quad) ----
        float tl = -1e30f, th = -1e30f;
#pragma unroll
        for (int ni = 0; ni < 8; ni++) {
            tl = fmaxf(tl, fmaxf(s[ni][0], s[ni][1]));
            th = fmaxf(th, fmaxf(s[ni][2], s[ni][3]));
        }
        tl = fmaxf(tl, __shfl_xor_sync(0xffffffffu, tl, 1));
        tl = fmaxf(tl, __shfl_xor_sync(0xffffffffu, tl, 2));
        th = fmaxf(th, __shfl_xor_sync(0xffffffffu, th, 1));
        th = fmaxf(th, __shfl_xor_sync(0xffffffffu, th, 2));

        float mn_lo = fmaxf(m_lo, tl);
        float mn_hi = fmaxf(m_hi, th);
        float al = __expf(m_lo - mn_lo);
        float ah = __expf(m_hi - mn_hi);

        // ---- exp + row sum ----
        float sl = 0.f, sh = 0.f;
#pragma unroll
        for (int ni = 0; ni < 8; ni++) {
            s[ni][0] = __expf(s[ni][0] - mn_lo);
            s[ni][1] = __expf(s[ni][1] - mn_lo);
            s[ni][2] = __expf(s[ni][2] - mn_hi);
            s[ni][3] = __expf(s[ni][3] - mn_hi);
            sl += s[ni][0] + s[ni][1];
            sh += s[ni][2] + s[ni][3];
        }
        sl += __shfl_xor_sync(0xffffffffu, sl, 1);
        sl += __shfl_xor_sync(0xffffffffu, sl, 2);
        sh += __shfl_xor_sync(0xffffffffu, sh, 1);
        sh += __shfl_xor_sync(0xffffffffu, sh, 2);

        l_lo = l_lo * al + sl;
        l_hi = l_hi * ah + sh;
        m_lo = mn_lo;
        m_hi = mn_hi;

        // ---- rescale O ----
#pragma unroll
        for (int nd = 0; nd < 8; nd++) {
            o[nd][0] *= al; o[nd][1] *= al;
            o[nd][2] *= ah; o[nd][3] *= ah;
        }

        // ---- PV: O += P @ V ----
        const int src0 = (lane & ~3) | (tg >> 1);
        const int src2 = src0 + 2;
        const bool odd = tg & 1;
#pragma unroll
        for (int j = 0; j < 8; j++) {
            float e0 = __shfl_sync(0xffffffffu, s[j][0], src0);
            float e1 = __shfl_sync(0xffffffffu, s[j][1], src0);
            float e2 = __shfl_sync(0xffffffffu, s[j][2], src0);
            float e3 = __shfl_sync(0xffffffffu, s[j][3], src0);
            float f0 = __shfl_sync(0xffffffffu, s[j][0], src2);
            float f1 = __shfl_sync(0xffffffffu, s[j][1], src2);
            float f2 = __shfl_sync(0xffffffffu, s[j][2], src2);
            float f3 = __shfl_sync(0xffffffffu, s[j][3], src2);
            uint32_t pa[4];
            pa[0] = fbits(to_tf32(odd ? e1 : e0));
            pa[1] = fbits(to_tf32(odd ? e3 : e2));
            pa[2] = fbits(to_tf32(odd ? f1 : f0));
            pa[3] = fbits(to_tf32(odd ? f3 : f2));
            const float* vr0 = &Vs[(j * 8 + tg    ) * F_LD];
            const float* vr1 = &Vs[(j * 8 + tg + 4) * F_LD];
#pragma unroll
            for (int nd = 0; nd < 8; nd++) {
                uint32_t bf[2];
                bf[0] = fbits(to_tf32(vr0[nd * 8 + g]));
                bf[1] = fbits(to_tf32(vr1[nd * 8 + g]));
                mma8(o[nd], pa, bf);
            }
        }
    }

    // ---- Epilogue: normalize, write merged-head attn ----
    float il_lo = 1.f / l_lo;
    float il_hi = 1.f / l_hi;
#pragma unroll
    for (int nd = 0; nd < 8; nd++) {
        int dc = nd * 8 + tg * 2;
        size_t off = ((size_t)(b * SS + q_lo)) * EE + h * DD + dc;
        *reinterpret_cast<float2*>(&g_attn[off]) =
            make_float2(o[nd][0] * il_lo, o[nd][1] * il_lo);
        *reinterpret_cast<float2*>(&g_attn[off + (size_t)8 * EE]) =
            make_float2(o[nd][2] * il_hi, o[nd][3] * il_hi);
    }
}

// ---------------------------------------------------------------------------
// Launch. Output layout: [ out (B*S*E) | present (2*B*H*NS*D) ]
// ---------------------------------------------------------------------------
extern "C" void kernel_launch(void* const* d_in, const int* in_sizes, int n_in,
                              void* d_out, int out_size)
{
    (void)in_sizes; (void)n_in; (void)out_size;
    const float* x      = (const float*)d_in[0];
    const float* past   = (const float*)d_in[1];
    const float* w_attn = (const float*)d_in[2];
    const float* b_attn = (const float*)d_in[3];
    const float* w_proj = (const float*)d_in[4];
    const float* b_proj = (const float*)d_in[5];

    float* out      = (float*)d_out;
    float* present  = out + (size_t)BB * SS * EE;
    float* presentK = present;
    float* presentV = present + (size_t)BB * HH * NSS * DD;

    // Opt-in to large dynamic smem (idempotent, not stream-ordered; safe under capture)
    cudaFuncSetAttribute(gemm_qkv_kernel,
                         cudaFuncAttributeMaxDynamicSharedMemorySize, GEMM_SMEM_BYTES);
    cudaFuncSetAttribute(gemm_proj_kernel,
                         cudaFuncAttributeMaxDynamicSharedMemorySize, GEMM_SMEM_BYTES);
    cudaFuncSetAttribute(flash_kernel,
                         cudaFuncAttributeMaxDynamicSharedMemorySize, FLASH_SMEM_BYTES);

    // 1) QKV = x @ w_attn + b_attn
    gemm_qkv_kernel<<<dim3(E3 / 128, (BB * SS) / 128), 256, GEMM_SMEM_BYTES>>>(x, w_attn, b_attn);

    // 2) present = concat(past, new K/V)
    {
        int n4 = 2 * BB * HH * NSS * (DD / 4);
        present_kernel<<<n4 / 256, 256>>>(past, present);
    }

    // 3) fused scores + softmax + PV (cp.async pipelined K/V)
    flash_kernel<<<dim3(SS / 128, BB * HH), 256, FLASH_SMEM_BYTES>>>(presentK, presentV);

    // 4) out = attn @ w_proj + b_proj
    gemm_proj_kernel<<<dim3(EE / 128, (BB * SS) / 128), 256, GEMM_SMEM_BYTES>>>(w_proj, b_proj, out);
}